// round 1
// baseline (speedup 1.0000x reference)
#include <cuda_runtime.h>

#define N_NODES 50000
#define N_EDGES 640000
#define HID 128
#define N_GRAPHS 512
#define AX_IN 64
#define AX_OUT 64
#define G_OUT 128
#define OUT_CH 8

// ---------------- device scratch (no allocations allowed) ----------------
__device__ int   g_src[N_EDGES];
__device__ int   g_dstv[N_EDGES];
__device__ int   g_csr[N_EDGES];
__device__ int   g_batch[N_NODES];
__device__ int   g_ecnt[N_NODES];
__device__ int   g_fill[N_NODES];
__device__ int   g_rowptr[N_NODES + 1];
__device__ float g_dinv[N_NODES];
__device__ int   g_gcnt[N_GRAPHS];
__device__ int   g_gptr[N_GRAPHS + 1];
__device__ float g_bufA[(size_t)N_NODES * HID];
__device__ float g_bufB[(size_t)N_NODES * HID];
__device__ float g_bufC[(size_t)N_NODES * HID];
__device__ float g_pooled[N_GRAPHS * HID];
__device__ int   g_is64;

__device__ __forceinline__ float* selbuf(int s) {
    return s == 0 ? g_bufA : (s == 1 ? g_bufB : g_bufC);
}

// ---------------- dtype detection: int64 vs int32 edge_index ----------------
// If edge_index is int64, node ids < 50000 => every high 32-bit word is 0.
// If int32, the odd-position words are random node ids (~never 0).
__global__ void k_detect(const int* ei) {
    int zeros = 0;
    for (int i = 0; i < 64; i++)
        if (ei[2 * i + 1] == 0) zeros++;
    g_is64 = (zeros >= 48) ? 1 : 0;
}

// ---------------- init counters ----------------
__global__ void k_init() {
    int i = blockIdx.x * blockDim.x + threadIdx.x;
    if (i < N_NODES) { g_ecnt[i] = 0; g_fill[i] = 0; }
    if (i < N_GRAPHS) g_gcnt[i] = 0;
}

// ---------------- convert edge_index / batch to int32 ----------------
__global__ void k_convert(const void* ei, const void* bt) {
    int is64 = g_is64;
    int i = blockIdx.x * blockDim.x + threadIdx.x;
    if (i < N_EDGES) {
        if (is64) {
            const long long* e = (const long long*)ei;
            g_src[i]  = (int)e[i];
            g_dstv[i] = (int)e[N_EDGES + i];
        } else {
            const int* e = (const int*)ei;
            g_src[i]  = e[i];
            g_dstv[i] = e[N_EDGES + i];
        }
    }
    if (i < N_NODES) {
        g_batch[i] = is64 ? (int)((const long long*)bt)[i] : ((const int*)bt)[i];
    }
}

// ---------------- histograms: in-degree (by dst) and nodes-per-graph ----------------
__global__ void k_hist() {
    int i = blockIdx.x * blockDim.x + threadIdx.x;
    if (i < N_EDGES) atomicAdd(&g_ecnt[g_dstv[i]], 1);
    if (i < N_NODES) atomicAdd(&g_gcnt[g_batch[i]], 1);
}

// ---------------- single-block scans: row_ptr (exclusive), dinv, graph_ptr ----------------
__device__ __forceinline__ int warp_incl_scan(int x, int lane) {
#pragma unroll
    for (int off = 1; off < 32; off <<= 1) {
        int t = __shfl_up_sync(0xffffffffu, x, off);
        if (lane >= off) x += t;
    }
    return x;
}

__global__ void k_scan() {
    __shared__ int ws[32];
    int tid = threadIdx.x, lane = tid & 31, wid = tid >> 5;
    int carry = 0;
    const int NT = (N_NODES + 1023) / 1024;
    for (int t = 0; t < NT; t++) {
        int i = t * 1024 + tid;
        int v = (i < N_NODES) ? g_ecnt[i] : 0;
        int x = warp_incl_scan(v, lane);
        if (lane == 31) ws[wid] = x;
        __syncthreads();
        if (wid == 0) {
            int y = ws[lane];
            y = warp_incl_scan(y, lane);
            ws[lane] = y;
        }
        __syncthreads();
        int woff = (wid > 0) ? ws[wid - 1] : 0;
        int excl = carry + woff + x - v;
        if (i < N_NODES) {
            g_rowptr[i] = excl;
            g_dinv[i] = rsqrtf((float)(v + 1));  // +1 self-loop
        }
        carry += ws[31];
        __syncthreads();
    }
    if (tid == 0) g_rowptr[N_NODES] = carry;
    __syncthreads();
    // graph offsets (512 values, one tile)
    {
        int v = (tid < N_GRAPHS) ? g_gcnt[tid] : 0;
        int x = warp_incl_scan(v, lane);
        if (lane == 31) ws[wid] = x;
        __syncthreads();
        if (wid == 0) {
            int y = ws[lane];
            y = warp_incl_scan(y, lane);
            ws[lane] = y;
        }
        __syncthreads();
        int woff = (wid > 0) ? ws[wid - 1] : 0;
        int excl = woff + x - v;
        if (tid < N_GRAPHS) g_gptr[tid] = excl;
        if (tid == 0) g_gptr[N_GRAPHS] = N_NODES;
    }
}

// ---------------- CSR fill (edges grouped by dst) ----------------
__global__ void k_fill() {
    int i = blockIdx.x * blockDim.x + threadIdx.x;
    if (i < N_EDGES) {
        int d = g_dstv[i];
        int p = g_rowptr[d] + atomicAdd(&g_fill[d], 1);
        g_csr[p] = g_src[i];
    }
}

// ---------------- GEMM: Y[N,128] = X[N,128] @ W[128,128] ----------------
// 64-row x 128-col tile per block, 256 threads, 8x4 register tile/thread.
__global__ void k_gemm128(const float* __restrict__ Xext, int insel, int outsel,
                          const float* __restrict__ W) {
    __shared__ float4 sW[32][32];   // 32 k x 128 cols (as 32 float4)
    __shared__ float  sX[64][36];   // 64 rows x 32 k (padded)
    const float* X = Xext ? Xext : selbuf(insel);
    float* Y = selbuf(outsel);

    int tid = threadIdx.x;
    int tx = tid & 31, ty = tid >> 5;
    int row0 = blockIdx.x * 64;
    if (row0 >= N_NODES) return;

    float4 acc[8];
#pragma unroll
    for (int r = 0; r < 8; r++) acc[r] = make_float4(0.f, 0.f, 0.f, 0.f);

    for (int kb = 0; kb < 4; kb++) {
        // load X tile: 64 rows x 32 k = 512 float4
#pragma unroll
        for (int j = 0; j < 2; j++) {
            int i = tid + j * 256;
            int r = i >> 3, kq = i & 7;
            int row = row0 + r;
            float4 v = make_float4(0.f, 0.f, 0.f, 0.f);
            if (row < N_NODES) v = ((const float4*)X)[row * 32 + kb * 8 + kq];
            *((float4*)&sX[r][kq * 4]) = v;
        }
        // load W tile: 32 k x 128 cols = 1024 float4
#pragma unroll
        for (int j = 0; j < 4; j++) {
            int i = tid + j * 256;
            int k = i >> 5, cq = i & 31;
            sW[k][cq] = ((const float4*)W)[(kb * 32 + k) * 32 + cq];
        }
        __syncthreads();
#pragma unroll
        for (int k = 0; k < 32; k++) {
            float4 wv = sW[k][tx];
#pragma unroll
            for (int r = 0; r < 8; r++) {
                float xs = sX[ty * 8 + r][k];
                acc[r].x += xs * wv.x;
                acc[r].y += xs * wv.y;
                acc[r].z += xs * wv.z;
                acc[r].w += xs * wv.w;
            }
        }
        __syncthreads();
    }
#pragma unroll
    for (int r = 0; r < 8; r++) {
        int row = row0 + ty * 8 + r;
        if (row < N_NODES) ((float4*)Y)[row * 32 + tx] = acc[r];
    }
}

// ---------------- GCN aggregation: out[n] = relu(dinv[n]*(dinv[n]*h[n] + sum dinv[s]*h[s]) + b)
// one warp per node, float4 per lane (128 cols = 32 float4)
__global__ void k_agg(int insel, int outsel, const float* __restrict__ bias) {
    const float* H = selbuf(insel);
    float* O = selbuf(outsel);
    int gw = (blockIdx.x * blockDim.x + threadIdx.x) >> 5;
    int lane = threadIdx.x & 31;
    if (gw >= N_NODES) return;
    int n = gw;
    float din = g_dinv[n];
    const float4* H4 = (const float4*)H;
    float4 h = H4[(size_t)n * 32 + lane];
    float4 acc = make_float4(din * h.x, din * h.y, din * h.z, din * h.w);
    int e0 = g_rowptr[n], e1 = g_rowptr[n + 1];
    for (int e = e0; e < e1; e++) {
        int s = g_csr[e];
        float w = g_dinv[s];
        float4 hs = H4[(size_t)s * 32 + lane];
        acc.x += w * hs.x;
        acc.y += w * hs.y;
        acc.z += w * hs.z;
        acc.w += w * hs.w;
    }
    float4 b = ((const float4*)bias)[lane];
    float4 o;
    o.x = fmaxf(din * acc.x + b.x, 0.f);
    o.y = fmaxf(din * acc.y + b.y, 0.f);
    o.z = fmaxf(din * acc.z + b.z, 0.f);
    o.w = fmaxf(din * acc.w + b.w, 0.f);
    ((float4*)O)[(size_t)n * 32 + lane] = o;
}

// ---------------- mean pool (batch is sorted -> contiguous ranges) ----------------
__global__ void k_pool() {
    int g = blockIdx.x;
    int c = threadIdx.x;  // 128
    const float* H = g_bufA;
    int r0 = g_gptr[g], r1 = g_gptr[g + 1];
    float s = 0.f;
    for (int r = r0; r < r1; r++) s += H[(size_t)r * HID + c];
    float cnt = (float)((r1 - r0) > 1 ? (r1 - r0) : 1);
    g_pooled[g * HID + c] = s / cnt;
}

// ---------------- head: lin1 + ax lin + concat + lin2 ----------------
__global__ void k_head(const float* __restrict__ ax,
                       const float* __restrict__ lin1W, const float* __restrict__ lin1b,
                       const float* __restrict__ axW, const float* __restrict__ axb,
                       const float* __restrict__ lin2W, const float* __restrict__ lin2b,
                       float* __restrict__ out) {
    int g = blockIdx.x;
    int t = threadIdx.x;  // 192
    __shared__ float sp[G_OUT];
    __shared__ float sa[AX_IN];
    __shared__ float z[G_OUT + AX_OUT];
    if (t < G_OUT) sp[t] = g_pooled[g * HID + t];
    else sa[t - G_OUT] = ax[g * AX_IN + (t - G_OUT)];
    __syncthreads();
    if (t < G_OUT) {
        float acc = lin1b[t];
#pragma unroll 8
        for (int k = 0; k < HID; k++) acc += sp[k] * lin1W[k * G_OUT + t];
        z[t] = acc;
    } else {
        int c = t - G_OUT;
        float acc = axb[c];
#pragma unroll 8
        for (int k = 0; k < AX_IN; k++) acc += sa[k] * axW[k * AX_OUT + c];
        z[t] = acc;
    }
    __syncthreads();
    if (t < OUT_CH) {
        float o = lin2b[t];
#pragma unroll 8
        for (int k = 0; k < G_OUT + AX_OUT; k++) o += z[k] * lin2W[k * OUT_CH + t];
        out[g * OUT_CH + t] = o;
    }
}

// ---------------- launch ----------------
extern "C" void kernel_launch(void* const* d_in, const int* in_sizes, int n_in,
                              void* d_out, int out_size) {
    const float* x     = (const float*)d_in[0];
    const void*  ei    = d_in[1];
    const void*  bt    = d_in[2];
    const float* ax    = (const float*)d_in[3];
    const float* W1    = (const float*)d_in[4];
    const float* b1    = (const float*)d_in[5];
    const float* W2    = (const float*)d_in[6];
    const float* b2    = (const float*)d_in[7];
    const float* lin1W = (const float*)d_in[8];
    const float* lin1b = (const float*)d_in[9];
    const float* axW   = (const float*)d_in[10];
    const float* axb   = (const float*)d_in[11];
    const float* lin2W = (const float*)d_in[12];
    const float* lin2b = (const float*)d_in[13];
    float* out = (float*)d_out;

    const int EB = (N_EDGES + 255) / 256;   // 2500
    const int NB = (N_NODES + 255) / 256;   // 196

    k_detect<<<1, 1>>>((const int*)ei);
    k_init<<<NB, 256>>>();
    k_convert<<<EB, 256>>>(ei, bt);
    k_hist<<<EB, 256>>>();
    k_scan<<<1, 1024>>>();
    k_fill<<<EB, 256>>>();

    const int GB = (N_NODES + 63) / 64;     // 782
    k_gemm128<<<GB, 256>>>(x, -1, 0, W1);                 // x @ W1 -> A
    k_agg<<<(N_NODES * 32 + 255) / 256, 256>>>(0, 1, b1); // agg(A) -> B (relu)
    k_gemm128<<<GB, 256>>>(nullptr, 1, 2, W2);            // B @ W2 -> C
    k_agg<<<(N_NODES * 32 + 255) / 256, 256>>>(2, 0, b2); // agg(C) -> A (relu)
    k_pool<<<N_GRAPHS, 128>>>();                          // A -> pooled
    k_head<<<N_GRAPHS, 192>>>(ax, lin1W, lin1b, axW, axb, lin2W, lin2b, out);
}

// round 2
// speedup vs baseline: 1.7248x; 1.7248x over previous
#include <cuda_runtime.h>

#define N_NODES 50000
#define N_EDGES 640000
#define HID 128
#define N_GRAPHS 512
#define AX_IN 64
#define AX_OUT 64
#define G_OUT 128
#define OUT_CH 8

// ---------------- device scratch (no allocations allowed) ----------------
__device__ int   g_csr[N_EDGES];
__device__ int   g_dstv[N_EDGES];
__device__ int   g_srcv[N_EDGES];
__device__ int   g_batch[N_NODES];
__device__ int   g_ecnt[N_NODES];   // in-degree (without self loop)
__device__ int   g_fill[N_NODES];
__device__ int   g_rowstart[N_NODES];
__device__ float g_dinv[N_NODES];
__device__ int   g_gptr[N_GRAPHS + 1];
__device__ int   g_ctr;
__device__ float g_bufA[(size_t)N_NODES * HID];
__device__ float g_bufB[(size_t)N_NODES * HID];
__device__ float g_bufC[(size_t)N_NODES * HID];

__device__ __forceinline__ float* selbuf(int s) {
    return s == 0 ? g_bufA : (s == 1 ? g_bufB : g_bufC);
}

// ---------------- init counters ----------------
__global__ void k_init() {
    int i = blockIdx.x * blockDim.x + threadIdx.x;
    if (i < N_NODES) { g_ecnt[i] = 0; g_fill[i] = 0; }
    if (i == 0) g_ctr = 0;
}

// ---------------- edge pass: dtype detect + convert + degree histogram ----------------
// int64 detection: node ids < 50000 => if data is int64, every high 32-bit
// word of the first 64 entries is 0. If int32, those words are random ids.
__global__ void k_prep_edges(const int* __restrict__ ei, const int* __restrict__ bt) {
    __shared__ int s_is64;
    if (threadIdx.x == 0) {
        int zeros = 0;
#pragma unroll
        for (int i = 0; i < 64; i++)
            if (ei[2 * i + 1] == 0) zeros++;
        s_is64 = (zeros >= 48) ? 1 : 0;
    }
    __syncthreads();
    int is64 = s_is64;
    int i = blockIdx.x * blockDim.x + threadIdx.x;
    if (i < N_EDGES) {
        int s, d;
        if (is64) {
            const long long* e = (const long long*)ei;
            s = (int)e[i];
            d = (int)e[N_EDGES + i];
        } else {
            s = ei[i];
            d = ei[N_EDGES + i];
        }
        g_srcv[i] = s;
        g_dstv[i] = d;
        atomicAdd(&g_ecnt[d], 1);
    }
    if (i < N_NODES) {
        g_batch[i] = is64 ? (int)((const long long*)bt)[i] : bt[i];
    }
}

// ---------------- offsets: rowstart via atomic bump; dinv; graph boundaries ----------------
// CSR rows only need DISJOINT ranges, not sorted ones -> no prefix scan needed.
__global__ void k_offsets() {
    int i = blockIdx.x * blockDim.x + threadIdx.x;
    if (i >= N_NODES) return;
    int deg = g_ecnt[i];
    g_rowstart[i] = atomicAdd(&g_ctr, deg);
    g_dinv[i] = rsqrtf((float)(deg + 1));  // +1 self-loop
    // graph ptr from sorted batch ids (each gptr entry written exactly once)
    int b = g_batch[i];
    if (i == 0) {
        for (int g = 0; g <= b; g++) g_gptr[g] = 0;
    } else {
        int pb = g_batch[i - 1];
        for (int g = pb + 1; g <= b; g++) g_gptr[g] = i;
    }
    if (i == N_NODES - 1) {
        for (int g = b + 1; g <= N_GRAPHS; g++) g_gptr[g] = N_NODES;
    }
}

// ---------------- CSR fill (edges grouped by dst) ----------------
__global__ void k_fill() {
    int i = blockIdx.x * blockDim.x + threadIdx.x;
    if (i < N_EDGES) {
        int d = g_dstv[i];
        int p = g_rowstart[d] + atomicAdd(&g_fill[d], 1);
        g_csr[p] = g_srcv[i];
    }
}

// ---------------- GEMM: Y[N,128] = X[N,128] @ W[128,128] ----------------
// 64-row x 128-col tile per block, 256 threads, 8x4 register tile/thread.
__global__ void k_gemm128(const float* __restrict__ Xext, int insel, int outsel,
                          const float* __restrict__ W) {
    __shared__ float4 sW[32][32];   // 32 k x 128 cols (as 32 float4)
    __shared__ float  sX[64][36];   // 64 rows x 32 k (padded)
    const float* X = Xext ? Xext : selbuf(insel);
    float* Y = selbuf(outsel);

    int tid = threadIdx.x;
    int tx = tid & 31, ty = tid >> 5;
    int row0 = blockIdx.x * 64;
    if (row0 >= N_NODES) return;

    float4 acc[8];
#pragma unroll
    for (int r = 0; r < 8; r++) acc[r] = make_float4(0.f, 0.f, 0.f, 0.f);

    for (int kb = 0; kb < 4; kb++) {
#pragma unroll
        for (int j = 0; j < 2; j++) {
            int i = tid + j * 256;
            int r = i >> 3, kq = i & 7;
            int row = row0 + r;
            float4 v = make_float4(0.f, 0.f, 0.f, 0.f);
            if (row < N_NODES) v = ((const float4*)X)[row * 32 + kb * 8 + kq];
            *((float4*)&sX[r][kq * 4]) = v;
        }
#pragma unroll
        for (int j = 0; j < 4; j++) {
            int i = tid + j * 256;
            int k = i >> 5, cq = i & 31;
            sW[k][cq] = ((const float4*)W)[(kb * 32 + k) * 32 + cq];
        }
        __syncthreads();
#pragma unroll
        for (int k = 0; k < 32; k++) {
            float4 wv = sW[k][tx];
#pragma unroll
            for (int r = 0; r < 8; r++) {
                float xs = sX[ty * 8 + r][k];
                acc[r].x += xs * wv.x;
                acc[r].y += xs * wv.y;
                acc[r].z += xs * wv.z;
                acc[r].w += xs * wv.w;
            }
        }
        __syncthreads();
    }
#pragma unroll
    for (int r = 0; r < 8; r++) {
        int row = row0 + ty * 8 + r;
        if (row < N_NODES) ((float4*)Y)[row * 32 + tx] = acc[r];
    }
}

// ---------------- GCN aggregation ----------------
// out[n] = relu(dinv[n]*(dinv[n]*h[n] + sum_s dinv[s]*h[s]) + b)
// one warp per node; neighbor ids loaded coalesced + shfl-broadcast;
// gathers unrolled x4 for MLP.
__global__ void k_agg(int insel, int outsel, const float* __restrict__ bias) {
    const float* H = selbuf(insel);
    float* O = selbuf(outsel);
    int n = (blockIdx.x * blockDim.x + threadIdx.x) >> 5;
    int lane = threadIdx.x & 31;
    if (n >= N_NODES) return;
    float din = g_dinv[n];
    const float4* H4 = (const float4*)H;
    float4 h = H4[(size_t)n * 32 + lane];
    float4 acc = make_float4(din * h.x, din * h.y, din * h.z, din * h.w);
    int e0 = g_rowstart[n];
    int deg = g_ecnt[n];
    for (int base = 0; base < deg; base += 32) {
        int m = deg - base;
        if (m > 32) m = 32;
        int idx = 0;
        float wgt = 0.f;
        if (lane < m) {
            idx = g_csr[e0 + base + lane];
            wgt = g_dinv[idx];
        }
        int j = 0;
        for (; j + 4 <= m; j += 4) {
            int s0 = __shfl_sync(0xffffffffu, idx, j);
            int s1 = __shfl_sync(0xffffffffu, idx, j + 1);
            int s2 = __shfl_sync(0xffffffffu, idx, j + 2);
            int s3 = __shfl_sync(0xffffffffu, idx, j + 3);
            float w0 = __shfl_sync(0xffffffffu, wgt, j);
            float w1 = __shfl_sync(0xffffffffu, wgt, j + 1);
            float w2 = __shfl_sync(0xffffffffu, wgt, j + 2);
            float w3 = __shfl_sync(0xffffffffu, wgt, j + 3);
            float4 v0 = H4[(size_t)s0 * 32 + lane];
            float4 v1 = H4[(size_t)s1 * 32 + lane];
            float4 v2 = H4[(size_t)s2 * 32 + lane];
            float4 v3 = H4[(size_t)s3 * 32 + lane];
            acc.x += w0 * v0.x; acc.y += w0 * v0.y; acc.z += w0 * v0.z; acc.w += w0 * v0.w;
            acc.x += w1 * v1.x; acc.y += w1 * v1.y; acc.z += w1 * v1.z; acc.w += w1 * v1.w;
            acc.x += w2 * v2.x; acc.y += w2 * v2.y; acc.z += w2 * v2.z; acc.w += w2 * v2.w;
            acc.x += w3 * v3.x; acc.y += w3 * v3.y; acc.z += w3 * v3.z; acc.w += w3 * v3.w;
        }
        for (; j < m; j++) {
            int s0 = __shfl_sync(0xffffffffu, idx, j);
            float w0 = __shfl_sync(0xffffffffu, wgt, j);
            float4 v0 = H4[(size_t)s0 * 32 + lane];
            acc.x += w0 * v0.x; acc.y += w0 * v0.y; acc.z += w0 * v0.z; acc.w += w0 * v0.w;
        }
    }
    float4 b = ((const float4*)bias)[lane];
    float4 o;
    o.x = fmaxf(din * acc.x + b.x, 0.f);
    o.y = fmaxf(din * acc.y + b.y, 0.f);
    o.z = fmaxf(din * acc.z + b.z, 0.f);
    o.w = fmaxf(din * acc.w + b.w, 0.f);
    ((float4*)O)[(size_t)n * 32 + lane] = o;
}

// ---------------- fused mean-pool + MLP head (block per graph) ----------------
__global__ void k_pool_head(const float* __restrict__ ax,
                            const float* __restrict__ lin1W, const float* __restrict__ lin1b,
                            const float* __restrict__ axW, const float* __restrict__ axb,
                            const float* __restrict__ lin2W, const float* __restrict__ lin2b,
                            float* __restrict__ out) {
    int g = blockIdx.x;
    int t = threadIdx.x;  // 192
    __shared__ float sp[G_OUT];
    __shared__ float sa[AX_IN];
    __shared__ float z[G_OUT + AX_OUT];
    const float* H = g_bufA;
    int r0 = g_gptr[g], r1 = g_gptr[g + 1];
    if (t < G_OUT) {
        float s = 0.f;
        for (int r = r0; r < r1; r++) s += H[(size_t)r * HID + t];
        float cnt = (float)((r1 - r0) > 1 ? (r1 - r0) : 1);
        sp[t] = s / cnt;
    } else {
        sa[t - G_OUT] = ax[g * AX_IN + (t - G_OUT)];
    }
    __syncthreads();
    if (t < G_OUT) {
        float acc = lin1b[t];
#pragma unroll 8
        for (int k = 0; k < HID; k++) acc += sp[k] * lin1W[k * G_OUT + t];
        z[t] = acc;
    } else {
        int c = t - G_OUT;
        float acc = axb[c];
#pragma unroll 8
        for (int k = 0; k < AX_IN; k++) acc += sa[k] * axW[k * AX_OUT + c];
        z[t] = acc;
    }
    __syncthreads();
    if (t < OUT_CH) {
        float o = lin2b[t];
#pragma unroll 8
        for (int k = 0; k < G_OUT + AX_OUT; k++) o += z[k] * lin2W[k * OUT_CH + t];
        out[g * OUT_CH + t] = o;
    }
}

// ---------------- launch ----------------
extern "C" void kernel_launch(void* const* d_in, const int* in_sizes, int n_in,
                              void* d_out, int out_size) {
    const float* x     = (const float*)d_in[0];
    const int*   ei    = (const int*)d_in[1];
    const int*   bt    = (const int*)d_in[2];
    const float* ax    = (const float*)d_in[3];
    const float* W1    = (const float*)d_in[4];
    const float* b1    = (const float*)d_in[5];
    const float* W2    = (const float*)d_in[6];
    const float* b2    = (const float*)d_in[7];
    const float* lin1W = (const float*)d_in[8];
    const float* lin1b = (const float*)d_in[9];
    const float* axW   = (const float*)d_in[10];
    const float* axb   = (const float*)d_in[11];
    const float* lin2W = (const float*)d_in[12];
    const float* lin2b = (const float*)d_in[13];
    float* out = (float*)d_out;

    const int EB = (N_EDGES + 255) / 256;   // 2500
    const int NB = (N_NODES + 255) / 256;   // 196

    k_init<<<NB, 256>>>();
    k_prep_edges<<<EB, 256>>>(ei, bt);
    k_offsets<<<NB, 256>>>();
    k_fill<<<EB, 256>>>();

    const int GB = (N_NODES + 63) / 64;     // 782
    k_gemm128<<<GB, 256>>>(x, -1, 0, W1);                 // x @ W1 -> A
    k_agg<<<(N_NODES * 32 + 255) / 256, 256>>>(0, 1, b1); // agg(A) -> B (relu)
    k_gemm128<<<GB, 256>>>(nullptr, 1, 2, W2);            // B @ W2 -> C
    k_agg<<<(N_NODES * 32 + 255) / 256, 256>>>(2, 0, b2); // agg(C) -> A (relu)
    k_pool_head<<<N_GRAPHS, 192>>>(ax, lin1W, lin1b, axW, axb, lin2W, lin2b, out);
}

// round 4
// speedup vs baseline: 1.8322x; 1.0622x over previous
#include <cuda_runtime.h>
#include <cuda_fp16.h>

#define N_NODES 50000
#define N_EDGES 640000
#define HID 128
#define N_GRAPHS 512
#define AX_IN 64
#define AX_OUT 64
#define G_OUT 128
#define OUT_CH 8

// ---------------- device scratch (16B-aligned via float4/int4) ----------------
__device__ int4  g_csr4[N_EDGES / 4];
__device__ int4  g_dstv4[N_EDGES / 4];
__device__ int4  g_srcv4[N_EDGES / 4];
__device__ int4  g_batch4[N_NODES / 4];
__device__ int4  g_ecnt4[N_NODES / 4];   // in-degree (without self loop)
__device__ int4  g_fill4[N_NODES / 4];
__device__ int   g_rowstart[N_NODES];
__device__ float g_dinv[N_NODES];
__device__ int   g_gptr[N_GRAPHS + 1];
__device__ int   g_ctr;
// half-precision intermediate feature buffers (declared float4 for 16B alignment)
__device__ float4 g_bufA[(size_t)N_NODES * HID / 8];
__device__ float4 g_bufB[(size_t)N_NODES * HID / 8];
__device__ float4 g_bufC[(size_t)N_NODES * HID / 8];

#define g_csr   ((int*)g_csr4)
#define g_dstv  ((int*)g_dstv4)
#define g_srcv  ((int*)g_srcv4)
#define g_batch ((int*)g_batch4)
#define g_ecnt  ((int*)g_ecnt4)
#define g_fill  ((int*)g_fill4)

__device__ __forceinline__ __half* selbuf(int s) {
    return (__half*)(s == 0 ? g_bufA : (s == 1 ? g_bufB : g_bufC));
}

// ---------------- init counters (vectorized) ----------------
__global__ void k_init() {
    int i = blockIdx.x * blockDim.x + threadIdx.x;
    if (i < N_NODES / 4) {
        int4 z = make_int4(0, 0, 0, 0);
        g_ecnt4[i] = z;
        g_fill4[i] = z;
    }
    if (i == 0) g_ctr = 0;
}

// ---------------- edge pass: dtype detect + convert + degree histogram ----------------
// int64 detection: node ids < 50000 => if data is int64, every high 32-bit
// word of the first 64 entries is 0. If int32, those words are random ids.
// 4 edges per thread, vectorized loads, 4 independent atomic chains.
__global__ void k_prep_edges(const int* __restrict__ ei, const int* __restrict__ bt) {
    __shared__ int s_is64;
    if (threadIdx.x == 0) {
        int zeros = 0;
#pragma unroll
        for (int i = 0; i < 64; i++)
            if (ei[2 * i + 1] == 0) zeros++;
        s_is64 = (zeros >= 48) ? 1 : 0;
    }
    __syncthreads();
    int is64 = s_is64;
    int t = blockIdx.x * blockDim.x + threadIdx.x;
    if (t < N_EDGES / 4) {
        int4 sv, dv;
        if (is64) {
            const longlong2* e = (const longlong2*)ei;
            longlong2 a = e[t * 2], b = e[t * 2 + 1];
            longlong2 c = e[N_EDGES / 2 + t * 2], d = e[N_EDGES / 2 + t * 2 + 1];
            sv = make_int4((int)a.x, (int)a.y, (int)b.x, (int)b.y);
            dv = make_int4((int)c.x, (int)c.y, (int)d.x, (int)d.y);
        } else {
            const int4* e = (const int4*)ei;
            sv = e[t];
            dv = e[N_EDGES / 4 + t];
        }
        g_srcv4[t] = sv;
        g_dstv4[t] = dv;
        atomicAdd(&g_ecnt[dv.x], 1);
        atomicAdd(&g_ecnt[dv.y], 1);
        atomicAdd(&g_ecnt[dv.z], 1);
        atomicAdd(&g_ecnt[dv.w], 1);
    }
    if (t < N_NODES / 4) {
        int4 bv;
        if (is64) {
            const longlong2* b = (const longlong2*)bt;
            longlong2 p = b[t * 2], q = b[t * 2 + 1];
            bv = make_int4((int)p.x, (int)p.y, (int)q.x, (int)q.y);
        } else {
            bv = ((const int4*)bt)[t];
        }
        g_batch4[t] = bv;
    }
}

// ---------------- offsets: rowstart via atomic bump; dinv; graph boundaries ----------------
// CSR rows only need DISJOINT ranges, not sorted ones -> no prefix scan needed.
__global__ void k_offsets() {
    int i = blockIdx.x * blockDim.x + threadIdx.x;
    if (i >= N_NODES) return;
    int deg = g_ecnt[i];
    g_rowstart[i] = atomicAdd(&g_ctr, deg);
    g_dinv[i] = rsqrtf((float)(deg + 1));  // +1 self-loop
    int b = g_batch[i];
    if (i == 0) {
        for (int g = 0; g <= b; g++) g_gptr[g] = 0;
    } else {
        int pb = g_batch[i - 1];
        for (int g = pb + 1; g <= b; g++) g_gptr[g] = i;
    }
    if (i == N_NODES - 1) {
        for (int g = b + 1; g <= N_GRAPHS; g++) g_gptr[g] = N_NODES;
    }
}

// ---------------- CSR fill: 4 edges/thread, independent chains ----------------
__global__ void k_fill() {
    int t = blockIdx.x * blockDim.x + threadIdx.x;
    if (t >= N_EDGES / 4) return;
    int4 sv = g_srcv4[t];
    int4 dv = g_dstv4[t];
    int p0 = g_rowstart[dv.x] + atomicAdd(&g_fill[dv.x], 1);
    int p1 = g_rowstart[dv.y] + atomicAdd(&g_fill[dv.y], 1);
    int p2 = g_rowstart[dv.z] + atomicAdd(&g_fill[dv.z], 1);
    int p3 = g_rowstart[dv.w] + atomicAdd(&g_fill[dv.w], 1);
    g_csr[p0] = sv.x;
    g_csr[p1] = sv.y;
    g_csr[p2] = sv.z;
    g_csr[p3] = sv.w;
}

// ---------------- GEMM: Y[N,128](half) = X[N,128] @ W[128,128] ----------------
// X is fp32 (external input) or fp16 (internal buffer). Compute fp32.
// 64-row x 128-col tile per block, 256 threads, 8x4 register tile/thread.
__global__ void k_gemm128(const float* __restrict__ Xf, int insel, int outsel,
                          const float* __restrict__ W) {
    __shared__ float4 sW[32][32];   // 32 k x 128 cols (as 32 float4)
    __shared__ float  sX[64][36];   // 64 rows x 32 k (padded)
    const __half* Xh = Xf ? (const __half*)0 : selbuf(insel);
    __half* Y = selbuf(outsel);

    int tid = threadIdx.x;
    int tx = tid & 31, ty = tid >> 5;
    int row0 = blockIdx.x * 64;
    if (row0 >= N_NODES) return;

    float4 acc[8];
#pragma unroll
    for (int r = 0; r < 8; r++) acc[r] = make_float4(0.f, 0.f, 0.f, 0.f);

    for (int kb = 0; kb < 4; kb++) {
        if (Xf) {
            // fp32 input: 64 rows x 32 k = 512 float4
#pragma unroll
            for (int j = 0; j < 2; j++) {
                int i = tid + j * 256;
                int r = i >> 3, kq = i & 7;
                int row = row0 + r;
                float4 v = make_float4(0.f, 0.f, 0.f, 0.f);
                if (row < N_NODES) v = ((const float4*)Xf)[row * 32 + kb * 8 + kq];
                *((float4*)&sX[r][kq * 4]) = v;
            }
        } else {
            // fp16 input: 64 rows x 32 k halves = 256 uint4 (8 halves each)
            int r = tid >> 2, q = tid & 3;
            int row = row0 + r;
            uint4 v = make_uint4(0, 0, 0, 0);
            if (row < N_NODES) v = ((const uint4*)Xh)[(size_t)row * 16 + kb * 4 + q];
            __half2* hp = (__half2*)&v;
#pragma unroll
            for (int u = 0; u < 4; u++) {
                float2 f = __half22float2(hp[u]);
                sX[r][q * 8 + u * 2] = f.x;
                sX[r][q * 8 + u * 2 + 1] = f.y;
            }
        }
#pragma unroll
        for (int j = 0; j < 4; j++) {
            int i = tid + j * 256;
            int k = i >> 5, cq = i & 31;
            sW[k][cq] = ((const float4*)W)[(kb * 32 + k) * 32 + cq];
        }
        __syncthreads();
#pragma unroll
        for (int k = 0; k < 32; k++) {
            float4 wv = sW[k][tx];
#pragma unroll
            for (int r = 0; r < 8; r++) {
                float xs = sX[ty * 8 + r][k];
                acc[r].x += xs * wv.x;
                acc[r].y += xs * wv.y;
                acc[r].z += xs * wv.z;
                acc[r].w += xs * wv.w;
            }
        }
        __syncthreads();
    }
#pragma unroll
    for (int r = 0; r < 8; r++) {
        int row = row0 + ty * 8 + r;
        if (row < N_NODES) {
            __half2 a = __floats2half2_rn(acc[r].x, acc[r].y);
            __half2 b = __floats2half2_rn(acc[r].z, acc[r].w);
            ((uint2*)Y)[(size_t)row * 32 + tx] =
                make_uint2(*(unsigned*)&a, *(unsigned*)&b);
        }
    }
}

// ---------------- GCN aggregation (half in / half out, fp32 accumulate) ----------------
// out[n] = relu(dinv[n]*(dinv[n]*h[n] + sum_s dinv[s]*h[s]) + b)
// one warp per node; lane covers 4 channels (uint2 = 4 halves).
__global__ void k_agg(int insel, int outsel, const float* __restrict__ bias) {
    const __half* H = selbuf(insel);
    __half* O = selbuf(outsel);
    int n = (blockIdx.x * blockDim.x + threadIdx.x) >> 5;
    int lane = threadIdx.x & 31;
    if (n >= N_NODES) return;
    float din = g_dinv[n];
    const uint2* H2 = (const uint2*)H;

    uint2 hr = H2[(size_t)n * 32 + lane];
    __half2* hp = (__half2*)&hr;
    float2 f0 = __half22float2(hp[0]), f1 = __half22float2(hp[1]);
    float4 acc = make_float4(din * f0.x, din * f0.y, din * f1.x, din * f1.y);

    int e0 = g_rowstart[n];
    int deg = g_ecnt[n];
    for (int base = 0; base < deg; base += 32) {
        int m = deg - base;
        if (m > 32) m = 32;
        int idx = 0;
        float wgt = 0.f;
        if (lane < m) {
            idx = g_csr[e0 + base + lane];
            wgt = g_dinv[idx];
        }
        int j = 0;
        for (; j + 4 <= m; j += 4) {
            int s0 = __shfl_sync(0xffffffffu, idx, j);
            int s1 = __shfl_sync(0xffffffffu, idx, j + 1);
            int s2 = __shfl_sync(0xffffffffu, idx, j + 2);
            int s3 = __shfl_sync(0xffffffffu, idx, j + 3);
            float w0 = __shfl_sync(0xffffffffu, wgt, j);
            float w1 = __shfl_sync(0xffffffffu, wgt, j + 1);
            float w2 = __shfl_sync(0xffffffffu, wgt, j + 2);
            float w3 = __shfl_sync(0xffffffffu, wgt, j + 3);
            uint2 v0 = H2[(size_t)s0 * 32 + lane];
            uint2 v1 = H2[(size_t)s1 * 32 + lane];
            uint2 v2 = H2[(size_t)s2 * 32 + lane];
            uint2 v3 = H2[(size_t)s3 * 32 + lane];
            {
                __half2* p = (__half2*)&v0;
                float2 a = __half22float2(p[0]), b = __half22float2(p[1]);
                acc.x += w0 * a.x; acc.y += w0 * a.y; acc.z += w0 * b.x; acc.w += w0 * b.y;
            }
            {
                __half2* p = (__half2*)&v1;
                float2 a = __half22float2(p[0]), b = __half22float2(p[1]);
                acc.x += w1 * a.x; acc.y += w1 * a.y; acc.z += w1 * b.x; acc.w += w1 * b.y;
            }
            {
                __half2* p = (__half2*)&v2;
                float2 a = __half22float2(p[0]), b = __half22float2(p[1]);
                acc.x += w2 * a.x; acc.y += w2 * a.y; acc.z += w2 * b.x; acc.w += w2 * b.y;
            }
            {
                __half2* p = (__half2*)&v3;
                float2 a = __half22float2(p[0]), b = __half22float2(p[1]);
                acc.x += w3 * a.x; acc.y += w3 * a.y; acc.z += w3 * b.x; acc.w += w3 * b.y;
            }
        }
        for (; j < m; j++) {
            int s0 = __shfl_sync(0xffffffffu, idx, j);
            float w0 = __shfl_sync(0xffffffffu, wgt, j);
            uint2 v0 = H2[(size_t)s0 * 32 + lane];
            __half2* p = (__half2*)&v0;
            float2 a = __half22float2(p[0]), b = __half22float2(p[1]);
            acc.x += w0 * a.x; acc.y += w0 * a.y; acc.z += w0 * b.x; acc.w += w0 * b.y;
        }
    }
    float4 b4 = ((const float4*)bias)[lane];
    float ox = fmaxf(din * acc.x + b4.x, 0.f);
    float oy = fmaxf(din * acc.y + b4.y, 0.f);
    float oz = fmaxf(din * acc.z + b4.z, 0.f);
    float ow = fmaxf(din * acc.w + b4.w, 0.f);
    __half2 oa = __floats2half2_rn(ox, oy);
    __half2 ob = __floats2half2_rn(oz, ow);
    ((uint2*)O)[(size_t)n * 32 + lane] = make_uint2(*(unsigned*)&oa, *(unsigned*)&ob);
}

// ---------------- fused mean-pool + MLP head (block per graph) ----------------
__global__ void k_pool_head(const float* __restrict__ ax,
                            const float* __restrict__ lin1W, const float* __restrict__ lin1b,
                            const float* __restrict__ axW, const float* __restrict__ axb,
                            const float* __restrict__ lin2W, const float* __restrict__ lin2b,
                            float* __restrict__ out) {
    int g = blockIdx.x;
    int t = threadIdx.x;  // 192
    __shared__ float sp[G_OUT];
    __shared__ float sa[AX_IN];
    __shared__ float z[G_OUT + AX_OUT];
    const __half* H = (const __half*)g_bufA;
    int r0 = g_gptr[g], r1 = g_gptr[g + 1];
    if (t < G_OUT) {
        float s = 0.f;
        for (int r = r0; r < r1; r++) s += __half2float(H[(size_t)r * HID + t]);
        float cnt = (float)((r1 - r0) > 1 ? (r1 - r0) : 1);
        sp[t] = s / cnt;
    } else {
        sa[t - G_OUT] = ax[g * AX_IN + (t - G_OUT)];
    }
    __syncthreads();
    if (t < G_OUT) {
        float acc = lin1b[t];
#pragma unroll 8
        for (int k = 0; k < HID; k++) acc += sp[k] * lin1W[k * G_OUT + t];
        z[t] = acc;
    } else {
        int c = t - G_OUT;
        float acc = axb[c];
#pragma unroll 8
        for (int k = 0; k < AX_IN; k++) acc += sa[k] * axW[k * AX_OUT + c];
        z[t] = acc;
    }
    __syncthreads();
    if (t < OUT_CH) {
        float o = lin2b[t];
#pragma unroll 8
        for (int k = 0; k < G_OUT + AX_OUT; k++) o += z[k] * lin2W[k * OUT_CH + t];
        out[g * OUT_CH + t] = o;
    }
}

// ---------------- launch ----------------
extern "C" void kernel_launch(void* const* d_in, const int* in_sizes, int n_in,
                              void* d_out, int out_size) {
    const float* x     = (const float*)d_in[0];
    const int*   ei    = (const int*)d_in[1];
    const int*   bt    = (const int*)d_in[2];
    const float* ax    = (const float*)d_in[3];
    const float* W1    = (const float*)d_in[4];
    const float* b1    = (const float*)d_in[5];
    const float* W2    = (const float*)d_in[6];
    const float* b2    = (const float*)d_in[7];
    const float* lin1W = (const float*)d_in[8];
    const float* lin1b = (const float*)d_in[9];
    const float* axW   = (const float*)d_in[10];
    const float* axb   = (const float*)d_in[11];
    const float* lin2W = (const float*)d_in[12];
    const float* lin2b = (const float*)d_in[13];
    float* out = (float*)d_out;

    const int EB4 = (N_EDGES / 4 + 255) / 256;   // 625
    const int NB  = (N_NODES + 255) / 256;       // 196
    const int IB  = (N_NODES / 4 + 255) / 256;   // 49

    k_init<<<IB, 256>>>();
    k_prep_edges<<<EB4, 256>>>(ei, bt);
    k_offsets<<<NB, 256>>>();
    k_fill<<<EB4, 256>>>();

    const int GB = (N_NODES + 63) / 64;          // 782
    k_gemm128<<<GB, 256>>>(x, -1, 0, W1);                 // x @ W1 -> A (half)
    k_agg<<<(N_NODES * 32 + 255) / 256, 256>>>(0, 1, b1); // agg(A) -> B (relu, half)
    k_gemm128<<<GB, 256>>>(nullptr, 1, 2, W2);            // B @ W2 -> C (half)
    k_agg<<<(N_NODES * 32 + 255) / 256, 256>>>(2, 0, b2); // agg(C) -> A (relu, half)
    k_pool_head<<<N_GRAPHS, 192>>>(ax, lin1W, lin1b, axW, axb, lin2W, lin2b, out);
}

// round 5
// speedup vs baseline: 1.8412x; 1.0049x over previous
#include <cuda_runtime.h>
#include <cuda_fp16.h>

#define N_NODES 50000
#define N_EDGES 640000
#define HID 128
#define N_GRAPHS 512
#define AX_IN 64
#define AX_OUT 64
#define G_OUT 128
#define OUT_CH 8

typedef unsigned long long ull;

// ---------------- device scratch (16B-aligned via float4/int4) ----------------
__device__ int4  g_csr4[N_EDGES / 4];
__device__ int4  g_dstv4[N_EDGES / 4];
__device__ int4  g_srcv4[N_EDGES / 4];
__device__ int4  g_batch4[N_NODES / 4];
__device__ int4  g_ecnt4[N_NODES / 4];   // in-degree (without self loop)
__device__ int4  g_fill4[N_NODES / 4];
__device__ int   g_rowstart[N_NODES];
__device__ float g_dinv[N_NODES];
__device__ int   g_gptr[N_GRAPHS + 1];
__device__ int   g_ctr;
// half-precision intermediate feature buffers (declared float4 for 16B alignment)
__device__ float4 g_bufA[(size_t)N_NODES * HID / 8];
__device__ float4 g_bufB[(size_t)N_NODES * HID / 8];
__device__ float4 g_bufC[(size_t)N_NODES * HID / 8];

#define g_csr   ((int*)g_csr4)
#define g_dstv  ((int*)g_dstv4)
#define g_srcv  ((int*)g_srcv4)
#define g_batch ((int*)g_batch4)
#define g_ecnt  ((int*)g_ecnt4)
#define g_fill  ((int*)g_fill4)

__device__ __forceinline__ __half* selbuf(int s) {
    return (__half*)(s == 0 ? g_bufA : (s == 1 ? g_bufB : g_bufC));
}

// ---------------- packed f32x2 helpers (Blackwell FFMA2) ----------------
__device__ __forceinline__ void fma2(ull& a, ull x, ull w) {
    asm("fma.rn.f32x2 %0, %1, %2, %0;" : "+l"(a) : "l"(x), "l"(w));
}
__device__ __forceinline__ ull pk(float lo, float hi) {
    ull r;
    asm("mov.b64 %0, {%1, %2};" : "=l"(r) : "f"(lo), "f"(hi));
    return r;
}
__device__ __forceinline__ void upk(float& lo, float& hi, ull v) {
    asm("mov.b64 {%0, %1}, %2;" : "=f"(lo), "=f"(hi) : "l"(v));
}

// ---------------- init counters (vectorized) ----------------
__global__ void k_init() {
    int i = blockIdx.x * blockDim.x + threadIdx.x;
    if (i < N_NODES / 4) {
        int4 z = make_int4(0, 0, 0, 0);
        g_ecnt4[i] = z;
        g_fill4[i] = z;
    }
    if (i == 0) g_ctr = 0;
}

// ---------------- edge pass: dtype detect + convert + degree histogram ----------------
__global__ void k_prep_edges(const int* __restrict__ ei, const int* __restrict__ bt) {
    __shared__ int s_is64;
    if (threadIdx.x == 0) {
        int zeros = 0;
#pragma unroll
        for (int i = 0; i < 64; i++)
            if (ei[2 * i + 1] == 0) zeros++;
        s_is64 = (zeros >= 48) ? 1 : 0;
    }
    __syncthreads();
    int is64 = s_is64;
    int t = blockIdx.x * blockDim.x + threadIdx.x;
    if (t < N_EDGES / 4) {
        int4 sv, dv;
        if (is64) {
            const longlong2* e = (const longlong2*)ei;
            longlong2 a = e[t * 2], b = e[t * 2 + 1];
            longlong2 c = e[N_EDGES / 2 + t * 2], d = e[N_EDGES / 2 + t * 2 + 1];
            sv = make_int4((int)a.x, (int)a.y, (int)b.x, (int)b.y);
            dv = make_int4((int)c.x, (int)c.y, (int)d.x, (int)d.y);
        } else {
            const int4* e = (const int4*)ei;
            sv = e[t];
            dv = e[N_EDGES / 4 + t];
        }
        g_srcv4[t] = sv;
        g_dstv4[t] = dv;
        atomicAdd(&g_ecnt[dv.x], 1);
        atomicAdd(&g_ecnt[dv.y], 1);
        atomicAdd(&g_ecnt[dv.z], 1);
        atomicAdd(&g_ecnt[dv.w], 1);
    }
    if (t < N_NODES / 4) {
        int4 bv;
        if (is64) {
            const longlong2* b = (const longlong2*)bt;
            longlong2 p = b[t * 2], q = b[t * 2 + 1];
            bv = make_int4((int)p.x, (int)p.y, (int)q.x, (int)q.y);
        } else {
            bv = ((const int4*)bt)[t];
        }
        g_batch4[t] = bv;
    }
}

// ---------------- offsets: rowstart via atomic bump; dinv; graph boundaries ----------------
__global__ void k_offsets() {
    int i = blockIdx.x * blockDim.x + threadIdx.x;
    if (i >= N_NODES) return;
    int deg = g_ecnt[i];
    g_rowstart[i] = atomicAdd(&g_ctr, deg);
    g_dinv[i] = rsqrtf((float)(deg + 1));  // +1 self-loop
    int b = g_batch[i];
    if (i == 0) {
        for (int g = 0; g <= b; g++) g_gptr[g] = 0;
    } else {
        int pb = g_batch[i - 1];
        for (int g = pb + 1; g <= b; g++) g_gptr[g] = i;
    }
    if (i == N_NODES - 1) {
        for (int g = b + 1; g <= N_GRAPHS; g++) g_gptr[g] = N_NODES;
    }
}

// ---------------- CSR fill: 4 edges/thread, independent chains ----------------
__global__ void k_fill() {
    int t = blockIdx.x * blockDim.x + threadIdx.x;
    if (t >= N_EDGES / 4) return;
    int4 sv = g_srcv4[t];
    int4 dv = g_dstv4[t];
    int p0 = g_rowstart[dv.x] + atomicAdd(&g_fill[dv.x], 1);
    int p1 = g_rowstart[dv.y] + atomicAdd(&g_fill[dv.y], 1);
    int p2 = g_rowstart[dv.z] + atomicAdd(&g_fill[dv.z], 1);
    int p3 = g_rowstart[dv.w] + atomicAdd(&g_fill[dv.w], 1);
    g_csr[p0] = sv.x;
    g_csr[p1] = sv.y;
    g_csr[p2] = sv.z;
    g_csr[p3] = sv.w;
}

// ---------------- GEMM: Y[N,128](half) = X[N,128] @ W[128,128] ----------------
// X fp32 (external) or fp16 (internal). fp32 math via packed fma.rn.f32x2.
// 64-row x 128-col tile, 256 threads, 8 rows x 4 cols per thread.
// X tile stored k-major (transposed) -> inner-loop row operands are two
// warp-uniform LDS.128 already packed as f32x2 row pairs.
__global__ void k_gemm128(const float* __restrict__ Xf, int insel, int outsel,
                          const float* __restrict__ W) {
    __shared__ float4 sW[32][32];    // 32 k x 128 cols
    __shared__ float  sXT[32][68];   // k-major: [k][row], 64 rows + pad
    const __half* Xh = Xf ? (const __half*)0 : selbuf(insel);
    __half* Y = selbuf(outsel);

    int tid = threadIdx.x;
    int tx = tid & 31, ty = tid >> 5;
    int row0 = blockIdx.x * 64;
    if (row0 >= N_NODES) return;

    ull acc[4][4];   // [row-pair][col] : {row 2rp, row 2rp+1}
#pragma unroll
    for (int rp = 0; rp < 4; rp++)
#pragma unroll
        for (int c = 0; c < 4; c++) acc[rp][c] = 0ull;  // {0.f,0.f}

    for (int kb = 0; kb < 4; kb++) {
        if (Xf) {
            // fp32 input: 512 float4 along k, stored transposed
#pragma unroll
            for (int j = 0; j < 2; j++) {
                int i = tid + j * 256;
                int r = i >> 3, kq = i & 7;
                int row = row0 + r;
                float4 v = make_float4(0.f, 0.f, 0.f, 0.f);
                if (row < N_NODES) v = ((const float4*)Xf)[row * 32 + kb * 8 + kq];
                sXT[kq * 4 + 0][r] = v.x;
                sXT[kq * 4 + 1][r] = v.y;
                sXT[kq * 4 + 2][r] = v.z;
                sXT[kq * 4 + 3][r] = v.w;
            }
        } else {
            // fp16 input: 8 halves along k per thread, stored transposed
            int r = tid >> 2, q = tid & 3;
            int row = row0 + r;
            uint4 v = make_uint4(0, 0, 0, 0);
            if (row < N_NODES) v = ((const uint4*)Xh)[(size_t)row * 16 + kb * 4 + q];
            __half2* hp = (__half2*)&v;
#pragma unroll
            for (int u = 0; u < 4; u++) {
                float2 f = __half22float2(hp[u]);
                sXT[q * 8 + u * 2][r] = f.x;
                sXT[q * 8 + u * 2 + 1][r] = f.y;
            }
        }
#pragma unroll
        for (int j = 0; j < 4; j++) {
            int i = tid + j * 256;
            int k = i >> 5, cq = i & 31;
            sW[k][cq] = ((const float4*)W)[(kb * 32 + k) * 32 + cq];
        }
        __syncthreads();
#pragma unroll
        for (int k = 0; k < 32; k++) {
            float4 wv = sW[k][tx];
            ull w0 = pk(wv.x, wv.x), w1 = pk(wv.y, wv.y);
            ull w2 = pk(wv.z, wv.z), w3 = pk(wv.w, wv.w);
            const ulonglong2* xp = (const ulonglong2*)&sXT[k][ty * 8];
            ulonglong2 xa = xp[0];   // {row0,row1},{row2,row3}
            ulonglong2 xb = xp[1];   // {row4,row5},{row6,row7}
            fma2(acc[0][0], xa.x, w0); fma2(acc[0][1], xa.x, w1);
            fma2(acc[0][2], xa.x, w2); fma2(acc[0][3], xa.x, w3);
            fma2(acc[1][0], xa.y, w0); fma2(acc[1][1], xa.y, w1);
            fma2(acc[1][2], xa.y, w2); fma2(acc[1][3], xa.y, w3);
            fma2(acc[2][0], xb.x, w0); fma2(acc[2][1], xb.x, w1);
            fma2(acc[2][2], xb.x, w2); fma2(acc[2][3], xb.x, w3);
            fma2(acc[3][0], xb.y, w0); fma2(acc[3][1], xb.y, w1);
            fma2(acc[3][2], xb.y, w2); fma2(acc[3][3], xb.y, w3);
        }
        __syncthreads();
    }
#pragma unroll
    for (int rp = 0; rp < 4; rp++) {
        float lo0, hi0, lo1, hi1, lo2, hi2, lo3, hi3;
        upk(lo0, hi0, acc[rp][0]);
        upk(lo1, hi1, acc[rp][1]);
        upk(lo2, hi2, acc[rp][2]);
        upk(lo3, hi3, acc[rp][3]);
        int rlo = row0 + ty * 8 + rp * 2;
        int rhi = rlo + 1;
        if (rlo < N_NODES) {
            __half2 a = __floats2half2_rn(lo0, lo1);
            __half2 b = __floats2half2_rn(lo2, lo3);
            ((uint2*)Y)[(size_t)rlo * 32 + tx] = make_uint2(*(unsigned*)&a, *(unsigned*)&b);
        }
        if (rhi < N_NODES) {
            __half2 a = __floats2half2_rn(hi0, hi1);
            __half2 b = __floats2half2_rn(hi2, hi3);
            ((uint2*)Y)[(size_t)rhi * 32 + tx] = make_uint2(*(unsigned*)&a, *(unsigned*)&b);
        }
    }
}

// ---------------- GCN aggregation (half in / half out, fp32 accumulate) ----------------
__global__ void k_agg(int insel, int outsel, const float* __restrict__ bias) {
    const __half* H = selbuf(insel);
    __half* O = selbuf(outsel);
    int n = (blockIdx.x * blockDim.x + threadIdx.x) >> 5;
    int lane = threadIdx.x & 31;
    if (n >= N_NODES) return;
    float din = g_dinv[n];
    const uint2* H2 = (const uint2*)H;

    uint2 hr = H2[(size_t)n * 32 + lane];
    __half2* hp = (__half2*)&hr;
    float2 f0 = __half22float2(hp[0]), f1 = __half22float2(hp[1]);
    float4 acc = make_float4(din * f0.x, din * f0.y, din * f1.x, din * f1.y);

    int e0 = g_rowstart[n];
    int deg = g_ecnt[n];
    for (int base = 0; base < deg; base += 32) {
        int m = deg - base;
        if (m > 32) m = 32;
        int idx = 0;
        float wgt = 0.f;
        if (lane < m) {
            idx = g_csr[e0 + base + lane];
            wgt = g_dinv[idx];
        }
        int j = 0;
        for (; j + 4 <= m; j += 4) {
            int s0 = __shfl_sync(0xffffffffu, idx, j);
            int s1 = __shfl_sync(0xffffffffu, idx, j + 1);
            int s2 = __shfl_sync(0xffffffffu, idx, j + 2);
            int s3 = __shfl_sync(0xffffffffu, idx, j + 3);
            float w0 = __shfl_sync(0xffffffffu, wgt, j);
            float w1 = __shfl_sync(0xffffffffu, wgt, j + 1);
            float w2 = __shfl_sync(0xffffffffu, wgt, j + 2);
            float w3 = __shfl_sync(0xffffffffu, wgt, j + 3);
            uint2 v0 = H2[(size_t)s0 * 32 + lane];
            uint2 v1 = H2[(size_t)s1 * 32 + lane];
            uint2 v2 = H2[(size_t)s2 * 32 + lane];
            uint2 v3 = H2[(size_t)s3 * 32 + lane];
            {
                __half2* p = (__half2*)&v0;
                float2 a = __half22float2(p[0]), b = __half22float2(p[1]);
                acc.x += w0 * a.x; acc.y += w0 * a.y; acc.z += w0 * b.x; acc.w += w0 * b.y;
            }
            {
                __half2* p = (__half2*)&v1;
                float2 a = __half22float2(p[0]), b = __half22float2(p[1]);
                acc.x += w1 * a.x; acc.y += w1 * a.y; acc.z += w1 * b.x; acc.w += w1 * b.y;
            }
            {
                __half2* p = (__half2*)&v2;
                float2 a = __half22float2(p[0]), b = __half22float2(p[1]);
                acc.x += w2 * a.x; acc.y += w2 * a.y; acc.z += w2 * b.x; acc.w += w2 * b.y;
            }
            {
                __half2* p = (__half2*)&v3;
                float2 a = __half22float2(p[0]), b = __half22float2(p[1]);
                acc.x += w3 * a.x; acc.y += w3 * a.y; acc.z += w3 * b.x; acc.w += w3 * b.y;
            }
        }
        for (; j < m; j++) {
            int s0 = __shfl_sync(0xffffffffu, idx, j);
            float w0 = __shfl_sync(0xffffffffu, wgt, j);
            uint2 v0 = H2[(size_t)s0 * 32 + lane];
            __half2* p = (__half2*)&v0;
            float2 a = __half22float2(p[0]), b = __half22float2(p[1]);
            acc.x += w0 * a.x; acc.y += w0 * a.y; acc.z += w0 * b.x; acc.w += w0 * b.y;
        }
    }
    float4 b4 = ((const float4*)bias)[lane];
    float ox = fmaxf(din * acc.x + b4.x, 0.f);
    float oy = fmaxf(din * acc.y + b4.y, 0.f);
    float oz = fmaxf(din * acc.z + b4.z, 0.f);
    float ow = fmaxf(din * acc.w + b4.w, 0.f);
    __half2 oa = __floats2half2_rn(ox, oy);
    __half2 ob = __floats2half2_rn(oz, ow);
    ((uint2*)O)[(size_t)n * 32 + lane] = make_uint2(*(unsigned*)&oa, *(unsigned*)&ob);
}

// ---------------- fused mean-pool + MLP head (block per graph) ----------------
__global__ void k_pool_head(const float* __restrict__ ax,
                            const float* __restrict__ lin1W, const float* __restrict__ lin1b,
                            const float* __restrict__ axW, const float* __restrict__ axb,
                            const float* __restrict__ lin2W, const float* __restrict__ lin2b,
                            float* __restrict__ out) {
    int g = blockIdx.x;
    int t = threadIdx.x;  // 192
    __shared__ float sp[G_OUT];
    __shared__ float sa[AX_IN];
    __shared__ float z[G_OUT + AX_OUT];
    const __half* H = (const __half*)g_bufA;
    int r0 = g_gptr[g], r1 = g_gptr[g + 1];
    if (t < G_OUT) {
        float s = 0.f;
        for (int r = r0; r < r1; r++) s += __half2float(H[(size_t)r * HID + t]);
        float cnt = (float)((r1 - r0) > 1 ? (r1 - r0) : 1);
        sp[t] = s / cnt;
    } else {
        sa[t - G_OUT] = ax[g * AX_IN + (t - G_OUT)];
    }
    __syncthreads();
    if (t < G_OUT) {
        float acc = lin1b[t];
#pragma unroll 8
        for (int k = 0; k < HID; k++) acc += sp[k] * lin1W[k * G_OUT + t];
        z[t] = acc;
    } else {
        int c = t - G_OUT;
        float acc = axb[c];
#pragma unroll 8
        for (int k = 0; k < AX_IN; k++) acc += sa[k] * axW[k * AX_OUT + c];
        z[t] = acc;
    }
    __syncthreads();
    if (t < OUT_CH) {
        float o = lin2b[t];
#pragma unroll 8
        for (int k = 0; k < G_OUT + AX_OUT; k++) o += z[k] * lin2W[k * OUT_CH + t];
        out[g * OUT_CH + t] = o;
    }
}

// ---------------- launch ----------------
extern "C" void kernel_launch(void* const* d_in, const int* in_sizes, int n_in,
                              void* d_out, int out_size) {
    const float* x     = (const float*)d_in[0];
    const int*   ei    = (const int*)d_in[1];
    const int*   bt    = (const int*)d_in[2];
    const float* ax    = (const float*)d_in[3];
    const float* W1    = (const float*)d_in[4];
    const float* b1    = (const float*)d_in[5];
    const float* W2    = (const float*)d_in[6];
    const float* b2    = (const float*)d_in[7];
    const float* lin1W = (const float*)d_in[8];
    const float* lin1b = (const float*)d_in[9];
    const float* axW   = (const float*)d_in[10];
    const float* axb   = (const float*)d_in[11];
    const float* lin2W = (const float*)d_in[12];
    const float* lin2b = (const float*)d_in[13];
    float* out = (float*)d_out;

    const int EB4 = (N_EDGES / 4 + 255) / 256;   // 625
    const int NB  = (N_NODES + 255) / 256;       // 196
    const int IB  = (N_NODES / 4 + 255) / 256;   // 49

    k_init<<<IB, 256>>>();
    k_prep_edges<<<EB4, 256>>>(ei, bt);
    k_offsets<<<NB, 256>>>();
    k_fill<<<EB4, 256>>>();

    const int GB = (N_NODES + 63) / 64;          // 782
    k_gemm128<<<GB, 256>>>(x, -1, 0, W1);                 // x @ W1 -> A (half)
    k_agg<<<(N_NODES * 32 + 255) / 256, 256>>>(0, 1, b1); // agg(A) -> B (relu, half)
    k_gemm128<<<GB, 256>>>(nullptr, 1, 2, W2);            // B @ W2 -> C (half)
    k_agg<<<(N_NODES * 32 + 255) / 256, 256>>>(2, 0, b2); // agg(C) -> A (relu, half)
    k_pool_head<<<N_GRAPHS, 192>>>(ax, lin1W, lin1b, axW, axb, lin2W, lin2b, out);
}

// round 7
// speedup vs baseline: 1.9853x; 1.0783x over previous
#include <cuda_runtime.h>
#include <cuda_fp16.h>

#define N_NODES 50000
#define N_EDGES 640000
#define HID 128
#define N_GRAPHS 512
#define AX_IN 64
#define AX_OUT 64
#define G_OUT 128
#define OUT_CH 8

typedef unsigned long long ull;

// ---------------- device scratch (16B-aligned via float4/int4) ----------------
__device__ int4  g_csr4[N_EDGES / 4];
__device__ int4  g_dstv4[N_EDGES / 4];
__device__ int4  g_srcv4[N_EDGES / 4];
__device__ int4  g_rank4[N_EDGES / 4];
__device__ int4  g_batch4[N_NODES / 4];
__device__ int4  g_ecnt4[N_NODES / 4];   // in-degree (without self loop)
__device__ int   g_rowstart[N_NODES];
__device__ float g_dinv[N_NODES];
__device__ int   g_gptr[N_GRAPHS + 1];
__device__ int   g_ctr;
// half-precision intermediate feature buffers (declared float4 for 16B alignment)
__device__ float4 g_bufA[(size_t)N_NODES * HID / 8];
__device__ float4 g_bufB[(size_t)N_NODES * HID / 8];
__device__ float4 g_bufC[(size_t)N_NODES * HID / 8];

#define g_csr   ((int*)g_csr4)
#define g_dstv  ((int*)g_dstv4)
#define g_srcv  ((int*)g_srcv4)
#define g_rank  ((int*)g_rank4)
#define g_batch ((int*)g_batch4)
#define g_ecnt  ((int*)g_ecnt4)

__device__ __forceinline__ __half* selbuf(int s) {
    return (__half*)(s == 0 ? g_bufA : (s == 1 ? g_bufB : g_bufC));
}

// ---------------- packed f32x2 helpers (Blackwell FFMA2) ----------------
__device__ __forceinline__ void fma2(ull& a, ull x, ull w) {
    asm("fma.rn.f32x2 %0, %1, %2, %0;" : "+l"(a) : "l"(x), "l"(w));
}
__device__ __forceinline__ ull pk(float lo, float hi) {
    ull r;
    asm("mov.b64 %0, {%1, %2};" : "=l"(r) : "f"(lo), "f"(hi));
    return r;
}
__device__ __forceinline__ void upk(float& lo, float& hi, ull v) {
    asm("mov.b64 {%0, %1}, %2;" : "=f"(lo), "=f"(hi) : "l"(v));
}

// ---------------- init counters (vectorized) ----------------
__global__ void k_init() {
    int i = blockIdx.x * blockDim.x + threadIdx.x;
    if (i < N_NODES / 4) g_ecnt4[i] = make_int4(0, 0, 0, 0);
    if (i == 0) g_ctr = 0;
}

// ---------------- GEMM core (shared by fused + standalone kernels) ----------------
// Y[64 rows, 128 cols](half) = X @ W, fp32 math via packed fma.rn.f32x2.
// X from fp32 global (Xf) when non-null, else fp16 buffer Xh.
__device__ __forceinline__ void gemm_tile(const float* __restrict__ Xf,
                                          const __half* __restrict__ Xh,
                                          __half* __restrict__ Y,
                                          const float* __restrict__ W,
                                          int row0,
                                          float4 (*sW)[32], float (*sXT)[68]) {
    int tid = threadIdx.x;
    int tx = tid & 31, ty = tid >> 5;

    ull acc[4][4];
#pragma unroll
    for (int rp = 0; rp < 4; rp++)
#pragma unroll
        for (int c = 0; c < 4; c++) acc[rp][c] = 0ull;

    for (int kb = 0; kb < 4; kb++) {
        if (Xf) {
#pragma unroll
            for (int j = 0; j < 2; j++) {
                int i = tid + j * 256;
                int r = i >> 3, kq = i & 7;
                int row = row0 + r;
                float4 v = make_float4(0.f, 0.f, 0.f, 0.f);
                if (row < N_NODES) v = ((const float4*)Xf)[row * 32 + kb * 8 + kq];
                sXT[kq * 4 + 0][r] = v.x;
                sXT[kq * 4 + 1][r] = v.y;
                sXT[kq * 4 + 2][r] = v.z;
                sXT[kq * 4 + 3][r] = v.w;
            }
        } else {
            int r = tid >> 2, q = tid & 3;
            int row = row0 + r;
            uint4 v = make_uint4(0, 0, 0, 0);
            if (row < N_NODES) v = ((const uint4*)Xh)[(size_t)row * 16 + kb * 4 + q];
            __half2* hp = (__half2*)&v;
#pragma unroll
            for (int u = 0; u < 4; u++) {
                float2 f = __half22float2(hp[u]);
                sXT[q * 8 + u * 2][r] = f.x;
                sXT[q * 8 + u * 2 + 1][r] = f.y;
            }
        }
#pragma unroll
        for (int j = 0; j < 4; j++) {
            int i = tid + j * 256;
            int k = i >> 5, cq = i & 31;
            sW[k][cq] = ((const float4*)W)[(kb * 32 + k) * 32 + cq];
        }
        __syncthreads();
#pragma unroll
        for (int k = 0; k < 32; k++) {
            float4 wv = sW[k][tx];
            ull w0 = pk(wv.x, wv.x), w1 = pk(wv.y, wv.y);
            ull w2 = pk(wv.z, wv.z), w3 = pk(wv.w, wv.w);
            const ulonglong2* xp = (const ulonglong2*)&sXT[k][ty * 8];
            ulonglong2 xa = xp[0];
            ulonglong2 xb = xp[1];
            fma2(acc[0][0], xa.x, w0); fma2(acc[0][1], xa.x, w1);
            fma2(acc[0][2], xa.x, w2); fma2(acc[0][3], xa.x, w3);
            fma2(acc[1][0], xa.y, w0); fma2(acc[1][1], xa.y, w1);
            fma2(acc[1][2], xa.y, w2); fma2(acc[1][3], xa.y, w3);
            fma2(acc[2][0], xb.x, w0); fma2(acc[2][1], xb.x, w1);
            fma2(acc[2][2], xb.x, w2); fma2(acc[2][3], xb.x, w3);
            fma2(acc[3][0], xb.y, w0); fma2(acc[3][1], xb.y, w1);
            fma2(acc[3][2], xb.y, w2); fma2(acc[3][3], xb.y, w3);
        }
        __syncthreads();
    }
#pragma unroll
    for (int rp = 0; rp < 4; rp++) {
        float lo0, hi0, lo1, hi1, lo2, hi2, lo3, hi3;
        upk(lo0, hi0, acc[rp][0]);
        upk(lo1, hi1, acc[rp][1]);
        upk(lo2, hi2, acc[rp][2]);
        upk(lo3, hi3, acc[rp][3]);
        int rlo = row0 + ty * 8 + rp * 2;
        int rhi = rlo + 1;
        if (rlo < N_NODES) {
            __half2 a = __floats2half2_rn(lo0, lo1);
            __half2 b = __floats2half2_rn(lo2, lo3);
            ((uint2*)Y)[(size_t)rlo * 32 + tx] = make_uint2(*(unsigned*)&a, *(unsigned*)&b);
        }
        if (rhi < N_NODES) {
            __half2 a = __floats2half2_rn(hi0, hi1);
            __half2 b = __floats2half2_rn(hi2, hi3);
            ((uint2*)Y)[(size_t)rhi * 32 + tx] = make_uint2(*(unsigned*)&a, *(unsigned*)&b);
        }
    }
}

#define GB_GEMM ((N_NODES + 63) / 64)   // 782
#define EB4     ((N_EDGES / 4 + 255) / 256)  // 625

// ---------------- fused: GEMM1 (blocks < GB_GEMM) + edge prep (rest) ----------------
// Edge prep: dtype detect + convert + degree histogram; the histogram atomic's
// return value IS the edge's rank within its dst row -> saved for atomic-free fill.
__global__ void k_prep_gemm(const float* __restrict__ x, const float* __restrict__ W1,
                            const int* __restrict__ ei, const int* __restrict__ bt) {
    __shared__ float4 sW[32][32];
    __shared__ float  sXT[32][68];
    if (blockIdx.x < GB_GEMM) {
        gemm_tile(x, (const __half*)0, selbuf(0), W1, blockIdx.x * 64, sW, sXT);
        return;
    }
    int bid = blockIdx.x - GB_GEMM;
    __shared__ int s_is64;
    if (threadIdx.x == 0) {
        int zeros = 0;
#pragma unroll
        for (int i = 0; i < 64; i++)
            if (ei[2 * i + 1] == 0) zeros++;
        s_is64 = (zeros >= 48) ? 1 : 0;
    }
    __syncthreads();
    int is64 = s_is64;
    int t = bid * blockDim.x + threadIdx.x;
    if (t < N_EDGES / 4) {
        int4 sv, dv;
        if (is64) {
            const longlong2* e = (const longlong2*)ei;
            longlong2 a = e[t * 2], b = e[t * 2 + 1];
            longlong2 c = e[N_EDGES / 2 + t * 2], d = e[N_EDGES / 2 + t * 2 + 1];
            sv = make_int4((int)a.x, (int)a.y, (int)b.x, (int)b.y);
            dv = make_int4((int)c.x, (int)c.y, (int)d.x, (int)d.y);
        } else {
            const int4* e = (const int4*)ei;
            sv = e[t];
            dv = e[N_EDGES / 4 + t];
        }
        g_srcv4[t] = sv;
        g_dstv4[t] = dv;
        int4 rk;
        rk.x = atomicAdd(&g_ecnt[dv.x], 1);
        rk.y = atomicAdd(&g_ecnt[dv.y], 1);
        rk.z = atomicAdd(&g_ecnt[dv.z], 1);
        rk.w = atomicAdd(&g_ecnt[dv.w], 1);
        g_rank4[t] = rk;
    }
    if (t < N_NODES / 4) {
        int4 bv;
        if (is64) {
            const longlong2* b = (const longlong2*)bt;
            longlong2 p = b[t * 2], q = b[t * 2 + 1];
            bv = make_int4((int)p.x, (int)p.y, (int)q.x, (int)q.y);
        } else {
            bv = ((const int4*)bt)[t];
        }
        g_batch4[t] = bv;
    }
}

// ---------------- offsets: rowstart via atomic bump; dinv; graph boundaries ----------------
__global__ void k_offsets() {
    int i = blockIdx.x * blockDim.x + threadIdx.x;
    if (i >= N_NODES) return;
    int deg = g_ecnt[i];
    g_rowstart[i] = atomicAdd(&g_ctr, deg);
    g_dinv[i] = rsqrtf((float)(deg + 1));  // +1 self-loop
    int b = g_batch[i];
    if (i == 0) {
        for (int g = 0; g <= b; g++) g_gptr[g] = 0;
    } else {
        int pb = g_batch[i - 1];
        for (int g = pb + 1; g <= b; g++) g_gptr[g] = i;
    }
    if (i == N_NODES - 1) {
        for (int g = b + 1; g <= N_GRAPHS; g++) g_gptr[g] = N_NODES;
    }
}

// ---------------- CSR fill: atomic-free scatter using saved ranks ----------------
__global__ void k_fill() {
    int t = blockIdx.x * blockDim.x + threadIdx.x;
    if (t >= N_EDGES / 4) return;
    int4 sv = g_srcv4[t];
    int4 dv = g_dstv4[t];
    int4 rk = g_rank4[t];
    g_csr[g_rowstart[dv.x] + rk.x] = sv.x;
    g_csr[g_rowstart[dv.y] + rk.y] = sv.y;
    g_csr[g_rowstart[dv.z] + rk.z] = sv.z;
    g_csr[g_rowstart[dv.w] + rk.w] = sv.w;
}

// ---------------- standalone GEMM (layer 2, fp16 input) ----------------
__global__ void k_gemm128(int insel, int outsel, const float* __restrict__ W) {
    __shared__ float4 sW[32][32];
    __shared__ float  sXT[32][68];
    int row0 = blockIdx.x * 64;
    if (row0 >= N_NODES) return;
    gemm_tile((const float*)0, selbuf(insel), selbuf(outsel), W, row0, sW, sXT);
}

// ---------------- GCN aggregation (half in / half out, fp32 accumulate) ----------------
__global__ void k_agg(int insel, int outsel, const float* __restrict__ bias) {
    const __half* H = selbuf(insel);
    __half* O = selbuf(outsel);
    int n = (blockIdx.x * blockDim.x + threadIdx.x) >> 5;
    int lane = threadIdx.x & 31;
    if (n >= N_NODES) return;
    float din = g_dinv[n];
    const uint2* H2 = (const uint2*)H;

    uint2 hr = H2[(size_t)n * 32 + lane];
    __half2* hp = (__half2*)&hr;
    float2 f0 = __half22float2(hp[0]), f1 = __half22float2(hp[1]);
    float4 acc = make_float4(din * f0.x, din * f0.y, din * f1.x, din * f1.y);

    int e0 = g_rowstart[n];
    int deg = g_ecnt[n];
    for (int base = 0; base < deg; base += 32) {
        int m = deg - base;
        if (m > 32) m = 32;
        int idx = 0;
        float wgt = 0.f;
        if (lane < m) {
            idx = g_csr[e0 + base + lane];
            wgt = g_dinv[idx];
        }
        int j = 0;
        for (; j + 4 <= m; j += 4) {
            int s0 = __shfl_sync(0xffffffffu, idx, j);
            int s1 = __shfl_sync(0xffffffffu, idx, j + 1);
            int s2 = __shfl_sync(0xffffffffu, idx, j + 2);
            int s3 = __shfl_sync(0xffffffffu, idx, j + 3);
            float w0 = __shfl_sync(0xffffffffu, wgt, j);
            float w1 = __shfl_sync(0xffffffffu, wgt, j + 1);
            float w2 = __shfl_sync(0xffffffffu, wgt, j + 2);
            float w3 = __shfl_sync(0xffffffffu, wgt, j + 3);
            uint2 v0 = H2[(size_t)s0 * 32 + lane];
            uint2 v1 = H2[(size_t)s1 * 32 + lane];
            uint2 v2 = H2[(size_t)s2 * 32 + lane];
            uint2 v3 = H2[(size_t)s3 * 32 + lane];
            {
                __half2* p = (__half2*)&v0;
                float2 a = __half22float2(p[0]), b = __half22float2(p[1]);
                acc.x += w0 * a.x; acc.y += w0 * a.y; acc.z += w0 * b.x; acc.w += w0 * b.y;
            }
            {
                __half2* p = (__half2*)&v1;
                float2 a = __half22float2(p[0]), b = __half22float2(p[1]);
                acc.x += w1 * a.x; acc.y += w1 * a.y; acc.z += w1 * b.x; acc.w += w1 * b.y;
            }
            {
                __half2* p = (__half2*)&v2;
                float2 a = __half22float2(p[0]), b = __half22float2(p[1]);
                acc.x += w2 * a.x; acc.y += w2 * a.y; acc.z += w2 * b.x; acc.w += w2 * b.y;
            }
            {
                __half2* p = (__half2*)&v3;
                float2 a = __half22float2(p[0]), b = __half22float2(p[1]);
                acc.x += w3 * a.x; acc.y += w3 * a.y; acc.z += w3 * b.x; acc.w += w3 * b.y;
            }
        }
        for (; j < m; j++) {
            int s0 = __shfl_sync(0xffffffffu, idx, j);
            float w0 = __shfl_sync(0xffffffffu, wgt, j);
            uint2 v0 = H2[(size_t)s0 * 32 + lane];
            __half2* p = (__half2*)&v0;
            float2 a = __half22float2(p[0]), b = __half22float2(p[1]);
            acc.x += w0 * a.x; acc.y += w0 * a.y; acc.z += w0 * b.x; acc.w += w0 * b.y;
        }
    }
    float4 b4 = ((const float4*)bias)[lane];
    float ox = fmaxf(din * acc.x + b4.x, 0.f);
    float oy = fmaxf(din * acc.y + b4.y, 0.f);
    float oz = fmaxf(din * acc.z + b4.z, 0.f);
    float ow = fmaxf(din * acc.w + b4.w, 0.f);
    __half2 oa = __floats2half2_rn(ox, oy);
    __half2 ob = __floats2half2_rn(oz, ow);
    ((uint2*)O)[(size_t)n * 32 + lane] = make_uint2(*(unsigned*)&oa, *(unsigned*)&ob);
}

// ---------------- fused mean-pool + MLP head (block per graph) ----------------
__global__ void k_pool_head(const float* __restrict__ ax,
                            const float* __restrict__ lin1W, const float* __restrict__ lin1b,
                            const float* __restrict__ axW, const float* __restrict__ axb,
                            const float* __restrict__ lin2W, const float* __restrict__ lin2b,
                            float* __restrict__ out) {
    int g = blockIdx.x;
    int t = threadIdx.x;  // 192
    __shared__ float sp[G_OUT];
    __shared__ float sa[AX_IN];
    __shared__ float z[G_OUT + AX_OUT];
    const __half* H = (const __half*)g_bufA;
    int r0 = g_gptr[g], r1 = g_gptr[g + 1];
    if (t < G_OUT) {
        float s = 0.f;
        for (int r = r0; r < r1; r++) s += __half2float(H[(size_t)r * HID + t]);
        float cnt = (float)((r1 - r0) > 1 ? (r1 - r0) : 1);
        sp[t] = s / cnt;
    } else {
        sa[t - G_OUT] = ax[g * AX_IN + (t - G_OUT)];
    }
    __syncthreads();
    if (t < G_OUT) {
        float acc = lin1b[t];
#pragma unroll 8
        for (int k = 0; k < HID; k++) acc += sp[k] * lin1W[k * G_OUT + t];
        z[t] = acc;
    } else {
        int c = t - G_OUT;
        float acc = axb[c];
#pragma unroll 8
        for (int k = 0; k < AX_IN; k++) acc += sa[k] * axW[k * AX_OUT + c];
        z[t] = acc;
    }
    __syncthreads();
    if (t < OUT_CH) {
        float o = lin2b[t];
#pragma unroll 8
        for (int k = 0; k < G_OUT + AX_OUT; k++) o += z[k] * lin2W[k * OUT_CH + t];
        out[g * OUT_CH + t] = o;
    }
}

// ---------------- launch ----------------
extern "C" void kernel_launch(void* const* d_in, const int* in_sizes, int n_in,
                              void* d_out, int out_size) {
    const float* x     = (const float*)d_in[0];
    const int*   ei    = (const int*)d_in[1];
    const int*   bt    = (const int*)d_in[2];
    const float* ax    = (const float*)d_in[3];
    const float* W1    = (const float*)d_in[4];
    const float* b1    = (const float*)d_in[5];
    const float* W2    = (const float*)d_in[6];
    const float* b2    = (const float*)d_in[7];
    const float* lin1W = (const float*)d_in[8];
    const float* lin1b = (const float*)d_in[9];
    const float* axW   = (const float*)d_in[10];
    const float* axb   = (const float*)d_in[11];
    const float* lin2W = (const float*)d_in[12];
    const float* lin2b = (const float*)d_in[13];
    float* out = (float*)d_out;

    const int NB = (N_NODES + 255) / 256;       // 196
    const int IB = (N_NODES / 4 + 255) / 256;   // 49

    k_init<<<IB, 256>>>();
    // GEMM1 (x@W1 -> A) runs concurrently with edge prep inside one launch
    k_prep_gemm<<<GB_GEMM + EB4, 256>>>(x, W1, ei, bt);
    k_offsets<<<NB, 256>>>();
    k_fill<<<EB4, 256>>>();

    k_agg<<<(N_NODES * 32 + 255) / 256, 256>>>(0, 1, b1); // agg(A) -> B (relu)
    k_gemm128<<<GB_GEMM, 256>>>(1, 2, W2);                // B @ W2 -> C
    k_agg<<<(N_NODES * 32 + 255) / 256, 256>>>(2, 0, b2); // agg(C) -> A (relu)
    k_pool_head<<<N_GRAPHS, 192>>>(ax, lin1W, lin1b, axW, axb, lin2W, lin2b, out);
}

// round 9
// speedup vs baseline: 1.9857x; 1.0002x over previous
#include <cuda_runtime.h>
#include <cuda_fp16.h>
#include <mma.h>

using namespace nvcuda;

#define N_NODES 50000
#define N_EDGES 640000
#define HID 128
#define N_GRAPHS 512
#define AX_IN 64
#define AX_OUT 64
#define G_OUT 128
#define OUT_CH 8

typedef unsigned long long ull;

// ---------------- device scratch (16B-aligned via float4/int4) ----------------
__device__ int4  g_csr4[N_EDGES / 4];
__device__ int4  g_dstv4[N_EDGES / 4];
__device__ int4  g_srcv4[N_EDGES / 4];
__device__ int4  g_rank4[N_EDGES / 4];
__device__ int4  g_batch4[N_NODES / 4];
__device__ int4  g_ecnt4[N_NODES / 4];   // in-degree (without self loop)
__device__ int   g_rowstart[N_NODES];
__device__ float g_dinv[N_NODES];
__device__ int   g_gptr[N_GRAPHS + 1];
__device__ int   g_ctr;
__device__ float4 g_pooled4[N_GRAPHS * HID / 4];
// half-precision intermediate feature buffers (declared float4 for 16B alignment)
__device__ float4 g_bufA[(size_t)N_NODES * HID / 8];
__device__ float4 g_bufB[(size_t)N_NODES * HID / 8];
__device__ float4 g_bufC[(size_t)N_NODES * HID / 8];

#define g_csr    ((int*)g_csr4)
#define g_dstv   ((int*)g_dstv4)
#define g_srcv   ((int*)g_srcv4)
#define g_rank   ((int*)g_rank4)
#define g_batch  ((int*)g_batch4)
#define g_ecnt   ((int*)g_ecnt4)
#define g_pooled ((float*)g_pooled4)

__device__ __forceinline__ __half* selbuf(int s) {
    return (__half*)(s == 0 ? g_bufA : (s == 1 ? g_bufB : g_bufC));
}

// ---------------- packed f32x2 helpers (Blackwell FFMA2) ----------------
__device__ __forceinline__ void fma2(ull& a, ull x, ull w) {
    asm("fma.rn.f32x2 %0, %1, %2, %0;" : "+l"(a) : "l"(x), "l"(w));
}
__device__ __forceinline__ ull pk(float lo, float hi) {
    ull r;
    asm("mov.b64 %0, {%1, %2};" : "=l"(r) : "f"(lo), "f"(hi));
    return r;
}
__device__ __forceinline__ void upk(float& lo, float& hi, ull v) {
    asm("mov.b64 {%0, %1}, %2;" : "=f"(lo), "=f"(hi) : "l"(v));
}

// ---------------- init counters (vectorized) ----------------
__global__ void k_init() {
    int i = blockIdx.x * blockDim.x + threadIdx.x;
    if (i < N_NODES / 4) g_ecnt4[i] = make_int4(0, 0, 0, 0);
    float4 z4 = make_float4(0.f, 0.f, 0.f, 0.f);
    for (int j = i; j < N_GRAPHS * HID / 4; j += gridDim.x * blockDim.x)
        g_pooled4[j] = z4;
    if (i == 0) g_ctr = 0;
}

// ---------------- GEMM1 tile core (fp32 input -> fp16 out, FFMA2) ----------------
__device__ __forceinline__ void gemm_tile(const float* __restrict__ Xf,
                                          __half* __restrict__ Y,
                                          const float* __restrict__ W,
                                          int row0,
                                          float4 (*sW)[32], float (*sXT)[68]) {
    int tid = threadIdx.x;
    int tx = tid & 31, ty = tid >> 5;

    ull acc[4][4];
#pragma unroll
    for (int rp = 0; rp < 4; rp++)
#pragma unroll
        for (int c = 0; c < 4; c++) acc[rp][c] = 0ull;

    for (int kb = 0; kb < 4; kb++) {
#pragma unroll
        for (int j = 0; j < 2; j++) {
            int i = tid + j * 256;
            int r = i >> 3, kq = i & 7;
            int row = row0 + r;
            float4 v = make_float4(0.f, 0.f, 0.f, 0.f);
            if (row < N_NODES) v = ((const float4*)Xf)[row * 32 + kb * 8 + kq];
            sXT[kq * 4 + 0][r] = v.x;
            sXT[kq * 4 + 1][r] = v.y;
            sXT[kq * 4 + 2][r] = v.z;
            sXT[kq * 4 + 3][r] = v.w;
        }
#pragma unroll
        for (int j = 0; j < 4; j++) {
            int i = tid + j * 256;
            int k = i >> 5, cq = i & 31;
            sW[k][cq] = ((const float4*)W)[(kb * 32 + k) * 32 + cq];
        }
        __syncthreads();
#pragma unroll
        for (int k = 0; k < 32; k++) {
            float4 wv = sW[k][tx];
            ull w0 = pk(wv.x, wv.x), w1 = pk(wv.y, wv.y);
            ull w2 = pk(wv.z, wv.z), w3 = pk(wv.w, wv.w);
            const ulonglong2* xp = (const ulonglong2*)&sXT[k][ty * 8];
            ulonglong2 xa = xp[0];
            ulonglong2 xb = xp[1];
            fma2(acc[0][0], xa.x, w0); fma2(acc[0][1], xa.x, w1);
            fma2(acc[0][2], xa.x, w2); fma2(acc[0][3], xa.x, w3);
            fma2(acc[1][0], xa.y, w0); fma2(acc[1][1], xa.y, w1);
            fma2(acc[1][2], xa.y, w2); fma2(acc[1][3], xa.y, w3);
            fma2(acc[2][0], xb.x, w0); fma2(acc[2][1], xb.x, w1);
            fma2(acc[2][2], xb.x, w2); fma2(acc[2][3], xb.x, w3);
            fma2(acc[3][0], xb.y, w0); fma2(acc[3][1], xb.y, w1);
            fma2(acc[3][2], xb.y, w2); fma2(acc[3][3], xb.y, w3);
        }
        __syncthreads();
    }
#pragma unroll
    for (int rp = 0; rp < 4; rp++) {
        float lo0, hi0, lo1, hi1, lo2, hi2, lo3, hi3;
        upk(lo0, hi0, acc[rp][0]);
        upk(lo1, hi1, acc[rp][1]);
        upk(lo2, hi2, acc[rp][2]);
        upk(lo3, hi3, acc[rp][3]);
        int rlo = row0 + ty * 8 + rp * 2;
        int rhi = rlo + 1;
        if (rlo < N_NODES) {
            __half2 a = __floats2half2_rn(lo0, lo1);
            __half2 b = __floats2half2_rn(lo2, lo3);
            ((uint2*)Y)[(size_t)rlo * 32 + tx] = make_uint2(*(unsigned*)&a, *(unsigned*)&b);
        }
        if (rhi < N_NODES) {
            __half2 a = __floats2half2_rn(hi0, hi1);
            __half2 b = __floats2half2_rn(hi2, hi3);
            ((uint2*)Y)[(size_t)rhi * 32 + tx] = make_uint2(*(unsigned*)&a, *(unsigned*)&b);
        }
    }
}

#define GB_GEMM ((N_NODES + 63) / 64)        // 782 GEMM1 tiles
#define EB4     ((N_EDGES / 4 + 255) / 256)  // 625
#define NB      ((N_NODES + 255) / 256)      // 196
// GEMM1 tile split across the three prep-chain kernels
#define T1 390
#define T2 590

// ---------------- fused: edge prep (blocks < EB4) + GEMM1 tiles [0,T1) ----------------
__global__ void k_prep_gemm(const float* __restrict__ x, const float* __restrict__ W1,
                            const int* __restrict__ ei, const int* __restrict__ bt) {
    __shared__ float4 sW[32][32];
    __shared__ float  sXT[32][68];
    if (blockIdx.x >= EB4) {
        gemm_tile(x, selbuf(0), W1, (blockIdx.x - EB4) * 64, sW, sXT);
        return;
    }
    __shared__ int s_is64;
    if (threadIdx.x == 0) {
        int zeros = 0;
#pragma unroll
        for (int i = 0; i < 64; i++)
            if (ei[2 * i + 1] == 0) zeros++;
        s_is64 = (zeros >= 48) ? 1 : 0;
    }
    __syncthreads();
    int is64 = s_is64;
    int t = blockIdx.x * blockDim.x + threadIdx.x;
    if (t < N_EDGES / 4) {
        int4 sv, dv;
        if (is64) {
            const longlong2* e = (const longlong2*)ei;
            longlong2 a = e[t * 2], b = e[t * 2 + 1];
            longlong2 c = e[N_EDGES / 2 + t * 2], d = e[N_EDGES / 2 + t * 2 + 1];
            sv = make_int4((int)a.x, (int)a.y, (int)b.x, (int)b.y);
            dv = make_int4((int)c.x, (int)c.y, (int)d.x, (int)d.y);
        } else {
            const int4* e = (const int4*)ei;
            sv = e[t];
            dv = e[N_EDGES / 4 + t];
        }
        g_srcv4[t] = sv;
        g_dstv4[t] = dv;
        int4 rk;
        rk.x = atomicAdd(&g_ecnt[dv.x], 1);
        rk.y = atomicAdd(&g_ecnt[dv.y], 1);
        rk.z = atomicAdd(&g_ecnt[dv.z], 1);
        rk.w = atomicAdd(&g_ecnt[dv.w], 1);
        g_rank4[t] = rk;
    }
    if (t < N_NODES / 4) {
        int4 bv;
        if (is64) {
            const longlong2* b = (const longlong2*)bt;
            longlong2 p = b[t * 2], q = b[t * 2 + 1];
            bv = make_int4((int)p.x, (int)p.y, (int)q.x, (int)q.y);
        } else {
            bv = ((const int4*)bt)[t];
        }
        g_batch4[t] = bv;
    }
}

// ---------------- fused: offsets (blocks < NB) + GEMM1 tiles [T1,T2) ----------------
__global__ void k_offsets_gemm(const float* __restrict__ x, const float* __restrict__ W1) {
    __shared__ float4 sW[32][32];
    __shared__ float  sXT[32][68];
    if (blockIdx.x >= NB) {
        gemm_tile(x, selbuf(0), W1, (T1 + (int)blockIdx.x - NB) * 64, sW, sXT);
        return;
    }
    int i = blockIdx.x * blockDim.x + threadIdx.x;
    if (i >= N_NODES) return;
    int deg = g_ecnt[i];
    g_rowstart[i] = atomicAdd(&g_ctr, deg);
    g_dinv[i] = rsqrtf((float)(deg + 1));  // +1 self-loop
    int b = g_batch[i];
    if (i == 0) {
        for (int g = 0; g <= b; g++) g_gptr[g] = 0;
    } else {
        int pb = g_batch[i - 1];
        for (int g = pb + 1; g <= b; g++) g_gptr[g] = i;
    }
    if (i == N_NODES - 1) {
        for (int g = b + 1; g <= N_GRAPHS; g++) g_gptr[g] = N_NODES;
    }
}

// ---------------- fused: CSR fill (blocks < EB4) + GEMM1 tiles [T2,GB_GEMM) ----------------
__global__ void k_fill_gemm(const float* __restrict__ x, const float* __restrict__ W1) {
    __shared__ float4 sW[32][32];
    __shared__ float  sXT[32][68];
    if (blockIdx.x >= EB4) {
        gemm_tile(x, selbuf(0), W1, (T2 + (int)blockIdx.x - EB4) * 64, sW, sXT);
        return;
    }
    int t = blockIdx.x * blockDim.x + threadIdx.x;
    if (t >= N_EDGES / 4) return;
    int4 sv = g_srcv4[t];
    int4 dv = g_dstv4[t];
    int4 rk = g_rank4[t];
    g_csr[g_rowstart[dv.x] + rk.x] = sv.x;
    g_csr[g_rowstart[dv.y] + rk.y] = sv.y;
    g_csr[g_rowstart[dv.z] + rk.z] = sv.z;
    g_csr[g_rowstart[dv.w] + rk.w] = sv.w;
}

// ---------------- GEMM2 via tensor cores (wmma, fp16 x fp16 -> fp32) ----------------
// Y[N,128](half) = X[N,128](half) @ W[128,128](fp32 -> fp16 in smem)
// 128-row block tile, 8 warps, each warp 16 rows x 128 cols.
__global__ void k_gemm_wmma(const float* __restrict__ Wf) {
    __shared__ __half sWh[128][136];
    __shared__ float  sAcc[8][16][16];
    const __half* X = selbuf(1);
    __half* Y = selbuf(2);
    int tid = threadIdx.x, wid = tid >> 5, lane = tid & 31;

    for (int i = tid; i < HID * HID; i += 256)
        sWh[i >> 7][i & 127] = __float2half(Wf[i]);
    __syncthreads();

    int row0 = blockIdx.x * 128 + wid * 16;
    if (row0 + 16 <= N_NODES) {
        wmma::fragment<wmma::accumulator, 16, 16, 16, float> acc[8];
#pragma unroll
        for (int c = 0; c < 8; c++) wmma::fill_fragment(acc[c], 0.f);
#pragma unroll
        for (int kb = 0; kb < 8; kb++) {
            wmma::fragment<wmma::matrix_a, 16, 16, 16, __half, wmma::row_major> a;
            wmma::load_matrix_sync(a, X + (size_t)row0 * 128 + kb * 16, 128);
#pragma unroll
            for (int c = 0; c < 8; c++) {
                wmma::fragment<wmma::matrix_b, 16, 16, 16, __half, wmma::row_major> b;
                wmma::load_matrix_sync(b, &sWh[kb * 16][c * 16], 136);
                wmma::mma_sync(acc[c], a, b, acc[c]);
            }
        }
#pragma unroll
        for (int c = 0; c < 8; c++) {
            wmma::store_matrix_sync(&sAcc[wid][0][0], acc[c], 16, wmma::mem_row_major);
            __syncwarp();
            int r = lane >> 1, cb = (lane & 1) * 8;
            const float* src = &sAcc[wid][r][cb];
            __half2 h0 = __floats2half2_rn(src[0], src[1]);
            __half2 h1 = __floats2half2_rn(src[2], src[3]);
            __half2 h2 = __floats2half2_rn(src[4], src[5]);
            __half2 h3 = __floats2half2_rn(src[6], src[7]);
            uint4 v = make_uint4(*(unsigned*)&h0, *(unsigned*)&h1,
                                 *(unsigned*)&h2, *(unsigned*)&h3);
            ((uint4*)Y)[(((size_t)(row0 + r)) * 128 + c * 16 + cb) >> 3] = v;
            __syncwarp();
        }
    }
}

// ---------------- agg core: compute one node's aggregated row ----------------
__device__ __forceinline__ float4 agg_row(const uint2* __restrict__ H2, int n, int lane,
                                          const float* __restrict__ bias) {
    float din = g_dinv[n];
    uint2 hr = H2[(size_t)n * 32 + lane];
    __half2* hp = (__half2*)&hr;
    float2 f0 = __half22float2(hp[0]), f1 = __half22float2(hp[1]);
    float4 acc = make_float4(din * f0.x, din * f0.y, din * f1.x, din * f1.y);

    int e0 = g_rowstart[n];
    int deg = g_ecnt[n];
    for (int base = 0; base < deg; base += 32) {
        int m = deg - base;
        if (m > 32) m = 32;
        int idx = 0;
        float wgt = 0.f;
        if (lane < m) {
            idx = g_csr[e0 + base + lane];
            wgt = g_dinv[idx];
        }
        int j = 0;
        for (; j + 4 <= m; j += 4) {
            int s0 = __shfl_sync(0xffffffffu, idx, j);
            int s1 = __shfl_sync(0xffffffffu, idx, j + 1);
            int s2 = __shfl_sync(0xffffffffu, idx, j + 2);
            int s3 = __shfl_sync(0xffffffffu, idx, j + 3);
            float w0 = __shfl_sync(0xffffffffu, wgt, j);
            float w1 = __shfl_sync(0xffffffffu, wgt, j + 1);
            float w2 = __shfl_sync(0xffffffffu, wgt, j + 2);
            float w3 = __shfl_sync(0xffffffffu, wgt, j + 3);
            uint2 v0 = H2[(size_t)s0 * 32 + lane];
            uint2 v1 = H2[(size_t)s1 * 32 + lane];
            uint2 v2 = H2[(size_t)s2 * 32 + lane];
            uint2 v3 = H2[(size_t)s3 * 32 + lane];
            {
                __half2* p = (__half2*)&v0;
                float2 a = __half22float2(p[0]), b = __half22float2(p[1]);
                acc.x += w0 * a.x; acc.y += w0 * a.y; acc.z += w0 * b.x; acc.w += w0 * b.y;
            }
            {
                __half2* p = (__half2*)&v1;
                float2 a = __half22float2(p[0]), b = __half22float2(p[1]);
                acc.x += w1 * a.x; acc.y += w1 * a.y; acc.z += w1 * b.x; acc.w += w1 * b.y;
            }
            {
                __half2* p = (__half2*)&v2;
                float2 a = __half22float2(p[0]), b = __half22float2(p[1]);
                acc.x += w2 * a.x; acc.y += w2 * a.y; acc.z += w2 * b.x; acc.w += w2 * b.y;
            }
            {
                __half2* p = (__half2*)&v3;
                float2 a = __half22float2(p[0]), b = __half22float2(p[1]);
                acc.x += w3 * a.x; acc.y += w3 * a.y; acc.z += w3 * b.x; acc.w += w3 * b.y;
            }
        }
        for (; j < m; j++) {
            int s0 = __shfl_sync(0xffffffffu, idx, j);
            float w0 = __shfl_sync(0xffffffffu, wgt, j);
            uint2 v0 = H2[(size_t)s0 * 32 + lane];
            __half2* p = (__half2*)&v0;
            float2 a = __half22float2(p[0]), b = __half22float2(p[1]);
            acc.x += w0 * a.x; acc.y += w0 * a.y; acc.z += w0 * b.x; acc.w += w0 * b.y;
        }
    }
    float4 b4 = ((const float4*)bias)[lane];
    float4 o;
    o.x = fmaxf(din * acc.x + b4.x, 0.f);
    o.y = fmaxf(din * acc.y + b4.y, 0.f);
    o.z = fmaxf(din * acc.z + b4.z, 0.f);
    o.w = fmaxf(din * acc.w + b4.w, 0.f);
    return o;
}

// ---------------- agg layer 1: bufA -> bufB ----------------
__global__ void k_agg(int insel, int outsel, const float* __restrict__ bias) {
    const uint2* H2 = (const uint2*)selbuf(insel);
    __half* O = selbuf(outsel);
    int n = (blockIdx.x * blockDim.x + threadIdx.x) >> 5;
    int lane = threadIdx.x & 31;
    if (n >= N_NODES) return;
    float4 o = agg_row(H2, n, lane, bias);
    __half2 oa = __floats2half2_rn(o.x, o.y);
    __half2 ob = __floats2half2_rn(o.z, o.w);
    ((uint2*)O)[(size_t)n * 32 + lane] = make_uint2(*(unsigned*)&oa, *(unsigned*)&ob);
}

// ---------------- agg layer 2 fused with pool-sum (bufC -> g_pooled) ----------------
// grid 6250 x 256: block covers 8 contiguous nodes; batch sorted -> few graphs/block.
__global__ void k_agg_pool(const float* __restrict__ bias) {
    __shared__ float sRow[8][132];
    const uint2* H2 = (const uint2*)selbuf(2);
    int tid = threadIdx.x;
    int wid = tid >> 5, lane = tid & 31;
    int n = blockIdx.x * 8 + wid;   // 6250*8 == N_NODES exactly
    float4 o = agg_row(H2, n, lane, bias);
    sRow[wid][lane * 4 + 0] = o.x;
    sRow[wid][lane * 4 + 1] = o.y;
    sRow[wid][lane * 4 + 2] = o.z;
    sRow[wid][lane * 4 + 3] = o.w;
    __syncthreads();
    if (tid < HID) {
        int c = tid;
        int nb = blockIdx.x * 8;
        int g = g_batch[nb];
        float acc = 0.f;
#pragma unroll
        for (int r = 0; r < 8; r++) {
            int gn = g_batch[nb + r];
            if (gn != g) {
                atomicAdd(&g_pooled[g * HID + c], acc);
                acc = 0.f;
                g = gn;
            }
            acc += sRow[r][c];
        }
        atomicAdd(&g_pooled[g * HID + c], acc);
    }
}

// ---------------- head: mean + lin1 + ax lin + concat + lin2 ----------------
__global__ void k_head(const float* __restrict__ ax,
                       const float* __restrict__ lin1W, const float* __restrict__ lin1b,
                       const float* __restrict__ axW, const float* __restrict__ axb,
                       const float* __restrict__ lin2W, const float* __restrict__ lin2b,
                       float* __restrict__ out) {
    int g = blockIdx.x;
    int t = threadIdx.x;  // 192
    __shared__ float sp[G_OUT];
    __shared__ float sa[AX_IN];
    __shared__ float z[G_OUT + AX_OUT];
    int cnt = g_gptr[g + 1] - g_gptr[g];
    float inv = 1.f / (float)(cnt > 1 ? cnt : 1);
    if (t < G_OUT) {
        sp[t] = g_pooled[g * HID + t] * inv;
    } else {
        sa[t - G_OUT] = ax[g * AX_IN + (t - G_OUT)];
    }
    __syncthreads();
    if (t < G_OUT) {
        float acc = lin1b[t];
#pragma unroll 8
        for (int k = 0; k < HID; k++) acc += sp[k] * lin1W[k * G_OUT + t];
        z[t] = acc;
    } else {
        int c = t - G_OUT;
        float acc = axb[c];
#pragma unroll 8
        for (int k = 0; k < AX_IN; k++) acc += sa[k] * axW[k * AX_OUT + c];
        z[t] = acc;
    }
    __syncthreads();
    if (t < OUT_CH) {
        float o = lin2b[t];
#pragma unroll 8
        for (int k = 0; k < G_OUT + AX_OUT; k++) o += z[k] * lin2W[k * OUT_CH + t];
        out[g * OUT_CH + t] = o;
    }
}

// ---------------- launch ----------------
extern "C" void kernel_launch(void* const* d_in, const int* in_sizes, int n_in,
                              void* d_out, int out_size) {
    const float* x     = (const float*)d_in[0];
    const int*   ei    = (const int*)d_in[1];
    const int*   bt    = (const int*)d_in[2];
    const float* ax    = (const float*)d_in[3];
    const float* W1    = (const float*)d_in[4];
    const float* b1    = (const float*)d_in[5];
    const float* W2    = (const float*)d_in[6];
    const float* b2    = (const float*)d_in[7];
    const float* lin1W = (const float*)d_in[8];
    const float* lin1b = (const float*)d_in[9];
    const float* axW   = (const float*)d_in[10];
    const float* axb   = (const float*)d_in[11];
    const float* lin2W = (const float*)d_in[12];
    const float* lin2b = (const float*)d_in[13];
    float* out = (float*)d_out;

    const int IB = (N_NODES / 4 + 255) / 256;   // 49

    k_init<<<IB, 256>>>();
    // GEMM1 tiles are spread across all three prep-chain kernels for overlap
    k_prep_gemm<<<EB4 + T1, 256>>>(x, W1, ei, bt);          // prep + tiles [0,T1)
    k_offsets_gemm<<<NB + (T2 - T1), 256>>>(x, W1);         // offsets + tiles [T1,T2)
    k_fill_gemm<<<EB4 + (GB_GEMM - T2), 256>>>(x, W1);      // fill + tiles [T2,782)

    k_agg<<<(N_NODES * 32 + 255) / 256, 256>>>(0, 1, b1);   // agg(A) -> B (relu)
    k_gemm_wmma<<<(N_NODES + 127) / 128, 256>>>(W2);        // B @ W2 -> C (tensor cores)
    k_agg_pool<<<N_NODES / 8, 256>>>(b2);                   // agg(C) + pool-sum -> g_pooled
    k_head<<<N_GRAPHS, 192>>>(ax, lin1W, lin1b, axW, axb, lin2W, lin2b, out);
}

// round 10
// speedup vs baseline: 2.6713x; 1.3453x over previous
#include <cuda_runtime.h>
#include <cuda_fp16.h>
#include <mma.h>

using namespace nvcuda;

#define N_NODES 50000
#define N_EDGES 640000
#define HID 128
#define N_GRAPHS 512
#define AX_IN 64
#define AX_OUT 64
#define G_OUT 128
#define OUT_CH 8
#define PAD 32            // padded CSR row stride
#define OVER_CAP 8192     // overflow capacity (deg>32 edges; expected ~0)

typedef unsigned long long ull;

// ---------------- device scratch ----------------
__device__ int4  g_csrp4[(size_t)N_NODES * PAD / 4];  // padded CSR
__device__ int2  g_over[OVER_CAP];
__device__ int   g_over_ctr;
__device__ int4  g_dstv4[N_EDGES / 4];
__device__ int4  g_srcv4[N_EDGES / 4];
__device__ int4  g_rank4[N_EDGES / 4];
__device__ int4  g_batch4[N_NODES / 4];
__device__ int4  g_ecnt4[N_NODES / 4];   // in-degree (without self loop)
__device__ int   g_gptr[N_GRAPHS + 1];
__device__ float4 g_pooled4[N_GRAPHS * HID / 4];
// half feature buffers (float4-declared for 16B alignment)
__device__ float4 g_bufA[(size_t)N_NODES * HID / 8];
__device__ float4 g_bufB[(size_t)N_NODES * HID / 8];
__device__ float4 g_bufC[(size_t)N_NODES * HID / 8];

#define g_csrp   ((int*)g_csrp4)
#define g_dstv   ((int*)g_dstv4)
#define g_srcv   ((int*)g_srcv4)
#define g_rank   ((int*)g_rank4)
#define g_batch  ((int*)g_batch4)
#define g_ecnt   ((int*)g_ecnt4)
#define g_pooled ((float*)g_pooled4)

__device__ __forceinline__ __half* selbuf(int s) {
    return (__half*)(s == 0 ? g_bufA : (s == 1 ? g_bufB : g_bufC));
}

// ---------------- init: zero counters + convert x fp32->fp16 into bufB ----------------
__global__ void k_init(const float* __restrict__ x) {
    int stride = gridDim.x * blockDim.x;
    int i0 = blockIdx.x * blockDim.x + threadIdx.x;
    int4 z = make_int4(0, 0, 0, 0);
    for (int i = i0; i < N_NODES / 4; i += stride) g_ecnt4[i] = z;
    float4 z4 = make_float4(0.f, 0.f, 0.f, 0.f);
    for (int i = i0; i < N_GRAPHS * HID / 4; i += stride) g_pooled4[i] = z4;
    uint2* xh = (uint2*)g_bufB;
    const float4* xf = (const float4*)x;
    for (int i = i0; i < N_NODES * HID / 4; i += stride) {
        float4 v = xf[i];
        __half2 a = __floats2half2_rn(v.x, v.y);
        __half2 b = __floats2half2_rn(v.z, v.w);
        xh[i] = make_uint2(*(unsigned*)&a, *(unsigned*)&b);
    }
    if (i0 == 0) g_over_ctr = 0;
}

// ---------------- prep: dtype detect + convert + degree histogram + gptr ----------------
__global__ void k_prep(const int* __restrict__ ei, const int* __restrict__ bt) {
    __shared__ int s_is64;
    if (threadIdx.x == 0) {
        int zeros = 0;
#pragma unroll
        for (int i = 0; i < 64; i++)
            if (ei[2 * i + 1] == 0) zeros++;
        s_is64 = (zeros >= 48) ? 1 : 0;
    }
    __syncthreads();
    int is64 = s_is64;
    int t = blockIdx.x * blockDim.x + threadIdx.x;
    if (t < N_EDGES / 4) {
        int4 sv, dv;
        if (is64) {
            const longlong2* e = (const longlong2*)ei;
            longlong2 a = e[t * 2], b = e[t * 2 + 1];
            longlong2 c = e[N_EDGES / 2 + t * 2], d = e[N_EDGES / 2 + t * 2 + 1];
            sv = make_int4((int)a.x, (int)a.y, (int)b.x, (int)b.y);
            dv = make_int4((int)c.x, (int)c.y, (int)d.x, (int)d.y);
        } else {
            const int4* e = (const int4*)ei;
            sv = e[t];
            dv = e[N_EDGES / 4 + t];
        }
        g_srcv4[t] = sv;
        g_dstv4[t] = dv;
        int4 rk;
        rk.x = atomicAdd(&g_ecnt[dv.x], 1);
        rk.y = atomicAdd(&g_ecnt[dv.y], 1);
        rk.z = atomicAdd(&g_ecnt[dv.z], 1);
        rk.w = atomicAdd(&g_ecnt[dv.w], 1);
        g_rank4[t] = rk;
    }
    if (t < N_NODES / 4) {
        int4 bv;
        if (is64) {
            const longlong2* b = (const longlong2*)bt;
            longlong2 p = b[t * 2], q = b[t * 2 + 1];
            bv = make_int4((int)p.x, (int)p.y, (int)q.x, (int)q.y);
        } else {
            bv = ((const int4*)bt)[t];
        }
        g_batch4[t] = bv;
    }
    // graph boundaries from sorted batch (each gptr entry written exactly once)
    if (t < N_NODES) {
        int b = is64 ? (int)((const long long*)bt)[t] : bt[t];
        int pb = -1;
        if (t > 0) pb = is64 ? (int)((const long long*)bt)[t - 1] : bt[t - 1];
        for (int g = pb + 1; g <= b; g++) g_gptr[g] = t;
        if (t == N_NODES - 1)
            for (int g = b + 1; g <= N_GRAPHS; g++) g_gptr[g] = N_NODES;
    }
}

// ---------------- fill: padded scatter (no rowstart, no atomics except overflow) ----------------
__global__ void k_fill() {
    int t = blockIdx.x * blockDim.x + threadIdx.x;
    if (t >= N_EDGES / 4) return;
    int4 sv = g_srcv4[t];
    int4 dv = g_dstv4[t];
    int4 rk = g_rank4[t];
#pragma unroll
    for (int u = 0; u < 4; u++) {
        int s = (&sv.x)[u], d = (&dv.x)[u], r = (&rk.x)[u];
        if (r < PAD) {
            g_csrp[d * PAD + r] = s;
        } else {
            int p = atomicAdd(&g_over_ctr, 1);
            if (p < OVER_CAP) g_over[p] = make_int2(d, s);
        }
    }
}

// ---------------- GEMM via tensor cores (wmma fp16 x fp16 -> fp32 -> fp16) ----------------
// Y[N,128] = X[N,128] @ W[128,128]; W fp32 in gmem -> fp16 smem.
__global__ void k_gemm_wmma(int insel, int outsel, const float* __restrict__ Wf) {
    __shared__ __half sWh[128][136];
    __shared__ float  sAcc[8][16][16];
    const __half* X = selbuf(insel);
    __half* Y = selbuf(outsel);
    int tid = threadIdx.x, wid = tid >> 5, lane = tid & 31;

    for (int i = tid; i < HID * HID; i += 256)
        sWh[i >> 7][i & 127] = __float2half(Wf[i]);
    __syncthreads();

    int row0 = blockIdx.x * 128 + wid * 16;
    if (row0 + 16 <= N_NODES) {
        wmma::fragment<wmma::accumulator, 16, 16, 16, float> acc[8];
#pragma unroll
        for (int c = 0; c < 8; c++) wmma::fill_fragment(acc[c], 0.f);
#pragma unroll
        for (int kb = 0; kb < 8; kb++) {
            wmma::fragment<wmma::matrix_a, 16, 16, 16, __half, wmma::row_major> a;
            wmma::load_matrix_sync(a, X + (size_t)row0 * 128 + kb * 16, 128);
#pragma unroll
            for (int c = 0; c < 8; c++) {
                wmma::fragment<wmma::matrix_b, 16, 16, 16, __half, wmma::row_major> b;
                wmma::load_matrix_sync(b, &sWh[kb * 16][c * 16], 136);
                wmma::mma_sync(acc[c], a, b, acc[c]);
            }
        }
#pragma unroll
        for (int c = 0; c < 8; c++) {
            wmma::store_matrix_sync(&sAcc[wid][0][0], acc[c], 16, wmma::mem_row_major);
            __syncwarp();
            int r = lane >> 1, cb = (lane & 1) * 8;
            const float* src = &sAcc[wid][r][cb];
            __half2 h0 = __floats2half2_rn(src[0], src[1]);
            __half2 h1 = __floats2half2_rn(src[2], src[3]);
            __half2 h2 = __floats2half2_rn(src[4], src[5]);
            __half2 h3 = __floats2half2_rn(src[6], src[7]);
            uint4 v = make_uint4(*(unsigned*)&h0, *(unsigned*)&h1,
                                 *(unsigned*)&h2, *(unsigned*)&h3);
            ((uint4*)Y)[(((size_t)(row0 + r)) * 128 + c * 16 + cb) >> 3] = v;
            __syncwarp();
        }
    }
}

// ---------------- agg core: one node's GCN-aggregated row (warp-collective) ----------------
__device__ __forceinline__ float4 agg_row(const uint2* __restrict__ H2, int n, int lane,
                                          const float* __restrict__ bias) {
    int degn = g_ecnt[n];
    float din = rsqrtf((float)(degn + 1));
    uint2 hr = H2[(size_t)n * 32 + lane];
    __half2* hp = (__half2*)&hr;
    float2 f0 = __half22float2(hp[0]), f1 = __half22float2(hp[1]);
    float4 acc = make_float4(din * f0.x, din * f0.y, din * f1.x, din * f1.y);

    int m = degn < PAD ? degn : PAD;
    int idx = 0;
    float wgt = 0.f;
    if (lane < m) {
        idx = g_csrp[n * PAD + lane];
        wgt = rsqrtf((float)(g_ecnt[idx] + 1));
    }
    int j = 0;
    for (; j + 4 <= m; j += 4) {
        int s0 = __shfl_sync(0xffffffffu, idx, j);
        int s1 = __shfl_sync(0xffffffffu, idx, j + 1);
        int s2 = __shfl_sync(0xffffffffu, idx, j + 2);
        int s3 = __shfl_sync(0xffffffffu, idx, j + 3);
        float w0 = __shfl_sync(0xffffffffu, wgt, j);
        float w1 = __shfl_sync(0xffffffffu, wgt, j + 1);
        float w2 = __shfl_sync(0xffffffffu, wgt, j + 2);
        float w3 = __shfl_sync(0xffffffffu, wgt, j + 3);
        uint2 v0 = H2[(size_t)s0 * 32 + lane];
        uint2 v1 = H2[(size_t)s1 * 32 + lane];
        uint2 v2 = H2[(size_t)s2 * 32 + lane];
        uint2 v3 = H2[(size_t)s3 * 32 + lane];
        {
            __half2* p = (__half2*)&v0;
            float2 a = __half22float2(p[0]), b = __half22float2(p[1]);
            acc.x += w0 * a.x; acc.y += w0 * a.y; acc.z += w0 * b.x; acc.w += w0 * b.y;
        }
        {
            __half2* p = (__half2*)&v1;
            float2 a = __half22float2(p[0]), b = __half22float2(p[1]);
            acc.x += w1 * a.x; acc.y += w1 * a.y; acc.z += w1 * b.x; acc.w += w1 * b.y;
        }
        {
            __half2* p = (__half2*)&v2;
            float2 a = __half22float2(p[0]), b = __half22float2(p[1]);
            acc.x += w2 * a.x; acc.y += w2 * a.y; acc.z += w2 * b.x; acc.w += w2 * b.y;
        }
        {
            __half2* p = (__half2*)&v3;
            float2 a = __half22float2(p[0]), b = __half22float2(p[1]);
            acc.x += w3 * a.x; acc.y += w3 * a.y; acc.z += w3 * b.x; acc.w += w3 * b.y;
        }
    }
    for (; j < m; j++) {
        int s0 = __shfl_sync(0xffffffffu, idx, j);
        float w0 = __shfl_sync(0xffffffffu, wgt, j);
        uint2 v0 = H2[(size_t)s0 * 32 + lane];
        __half2* p = (__half2*)&v0;
        float2 a = __half22float2(p[0]), b = __half22float2(p[1]);
        acc.x += w0 * a.x; acc.y += w0 * a.y; acc.z += w0 * b.x; acc.w += w0 * b.y;
    }
    // overflow edges (rank >= PAD): only nodes with deg > PAD scan the list
    if (degn > PAD) {
        int oc = g_over_ctr;
        if (oc > OVER_CAP) oc = OVER_CAP;
        for (int i = 0; i < oc; i++) {
            int2 o = g_over[i];
            if (o.x == n) {
                float w = rsqrtf((float)(g_ecnt[o.y] + 1));
                uint2 v = H2[(size_t)o.y * 32 + lane];
                __half2* p = (__half2*)&v;
                float2 a = __half22float2(p[0]), b = __half22float2(p[1]);
                acc.x += w * a.x; acc.y += w * a.y; acc.z += w * b.x; acc.w += w * b.y;
            }
        }
    }
    float4 b4 = ((const float4*)bias)[lane];
    float4 o;
    o.x = fmaxf(din * acc.x + b4.x, 0.f);
    o.y = fmaxf(din * acc.y + b4.y, 0.f);
    o.z = fmaxf(din * acc.z + b4.z, 0.f);
    o.w = fmaxf(din * acc.w + b4.w, 0.f);
    return o;
}

// ---------------- agg layer 1 ----------------
__global__ void k_agg(int insel, int outsel, const float* __restrict__ bias) {
    const uint2* H2 = (const uint2*)selbuf(insel);
    __half* O = selbuf(outsel);
    int n = (blockIdx.x * blockDim.x + threadIdx.x) >> 5;
    int lane = threadIdx.x & 31;
    if (n >= N_NODES) return;
    float4 o = agg_row(H2, n, lane, bias);
    __half2 oa = __floats2half2_rn(o.x, o.y);
    __half2 ob = __floats2half2_rn(o.z, o.w);
    ((uint2*)O)[(size_t)n * 32 + lane] = make_uint2(*(unsigned*)&oa, *(unsigned*)&ob);
}

// ---------------- agg layer 2 fused with pool-sum ----------------
__global__ void k_agg_pool(int insel, const float* __restrict__ bias) {
    __shared__ float sRow[8][132];
    const uint2* H2 = (const uint2*)selbuf(insel);
    int tid = threadIdx.x;
    int wid = tid >> 5, lane = tid & 31;
    int n = blockIdx.x * 8 + wid;   // 6250*8 == N_NODES exactly
    float4 o = agg_row(H2, n, lane, bias);
    sRow[wid][lane * 4 + 0] = o.x;
    sRow[wid][lane * 4 + 1] = o.y;
    sRow[wid][lane * 4 + 2] = o.z;
    sRow[wid][lane * 4 + 3] = o.w;
    __syncthreads();
    if (tid < HID) {
        int c = tid;
        int nb = blockIdx.x * 8;
        int g = g_batch[nb];
        float acc = 0.f;
#pragma unroll
        for (int r = 0; r < 8; r++) {
            int gn = g_batch[nb + r];
            if (gn != g) {
                atomicAdd(&g_pooled[g * HID + c], acc);
                acc = 0.f;
                g = gn;
            }
            acc += sRow[r][c];
        }
        atomicAdd(&g_pooled[g * HID + c], acc);
    }
}

// ---------------- head: mean + lin1 + ax lin + concat + lin2 ----------------
__global__ void k_head(const float* __restrict__ ax,
                       const float* __restrict__ lin1W, const float* __restrict__ lin1b,
                       const float* __restrict__ axW, const float* __restrict__ axb,
                       const float* __restrict__ lin2W, const float* __restrict__ lin2b,
                       float* __restrict__ out) {
    int g = blockIdx.x;
    int t = threadIdx.x;  // 192
    __shared__ float sp[G_OUT];
    __shared__ float sa[AX_IN];
    __shared__ float z[G_OUT + AX_OUT];
    int cnt = g_gptr[g + 1] - g_gptr[g];
    float inv = 1.f / (float)(cnt > 1 ? cnt : 1);
    if (t < G_OUT) {
        sp[t] = g_pooled[g * HID + t] * inv;
    } else {
        sa[t - G_OUT] = ax[g * AX_IN + (t - G_OUT)];
    }
    __syncthreads();
    if (t < G_OUT) {
        float acc = lin1b[t];
#pragma unroll 8
        for (int k = 0; k < HID; k++) acc += sp[k] * lin1W[k * G_OUT + t];
        z[t] = acc;
    } else {
        int c = t - G_OUT;
        float acc = axb[c];
#pragma unroll 8
        for (int k = 0; k < AX_IN; k++) acc += sa[k] * axW[k * AX_OUT + c];
        z[t] = acc;
    }
    __syncthreads();
    if (t < OUT_CH) {
        float o = lin2b[t];
#pragma unroll 8
        for (int k = 0; k < G_OUT + AX_OUT; k++) o += z[k] * lin2W[k * OUT_CH + t];
        out[g * OUT_CH + t] = o;
    }
}

// ---------------- launch ----------------
extern "C" void kernel_launch(void* const* d_in, const int* in_sizes, int n_in,
                              void* d_out, int out_size) {
    const float* x     = (const float*)d_in[0];
    const int*   ei    = (const int*)d_in[1];
    const int*   bt    = (const int*)d_in[2];
    const float* ax    = (const float*)d_in[3];
    const float* W1    = (const float*)d_in[4];
    const float* b1    = (const float*)d_in[5];
    const float* W2    = (const float*)d_in[6];
    const float* b2    = (const float*)d_in[7];
    const float* lin1W = (const float*)d_in[8];
    const float* lin1b = (const float*)d_in[9];
    const float* axW   = (const float*)d_in[10];
    const float* axb   = (const float*)d_in[11];
    const float* lin2W = (const float*)d_in[12];
    const float* lin2b = (const float*)d_in[13];
    float* out = (float*)d_out;

    const int EB4 = (N_EDGES / 4 + 255) / 256;   // 625
    const int GWB = (N_NODES + 127) / 128;       // 391

    k_init<<<2048, 256>>>(x);                     // zero + x -> fp16 (bufB)
    k_prep<<<EB4, 256>>>(ei, bt);                 // convert + hist/rank + gptr
    k_fill<<<EB4, 256>>>();                       // padded CSR scatter
    k_gemm_wmma<<<GWB, 256>>>(1, 0, W1);          // xh(B) @ W1 -> A
    k_agg<<<(N_NODES * 32) / 256, 256>>>(0, 1, b1);   // agg(A) -> B (relu)
    k_gemm_wmma<<<GWB, 256>>>(1, 2, W2);          // B @ W2 -> C
    k_agg_pool<<<N_NODES / 8, 256>>>(2, b2);      // agg(C) + pool-sum
    k_head<<<N_GRAPHS, 192>>>(ax, lin1W, lin1b, axW, axb, lin2W, lin2b, out);
}

// round 12
// speedup vs baseline: 2.8916x; 1.0825x over previous
#include <cuda_runtime.h>
#include <cuda_fp16.h>
#include <mma.h>

using namespace nvcuda;

#define N_NODES 50000
#define N_EDGES 640000
#define HID 128
#define N_GRAPHS 512
#define AX_IN 64
#define AX_OUT 64
#define G_OUT 128
#define OUT_CH 8
#define PAD 32            // padded CSR row stride
#define OVER_CAP 8192     // overflow capacity (deg>32 edges; expected ~0)
#define N_TILES (N_NODES / 16)   // 3125 row tiles of 16
#define GEMM_BLOCKS 296          // 2 per SM

typedef unsigned long long ull;

// ---------------- device scratch ----------------
__device__ int4  g_csrp4[(size_t)N_NODES * PAD / 4];  // padded CSR
__device__ int2  g_over[OVER_CAP];
__device__ int   g_over_ctr;
__device__ int4  g_dstv4[N_EDGES / 4];
__device__ int4  g_srcv4[N_EDGES / 4];
__device__ int4  g_rank4[N_EDGES / 4];
__device__ int4  g_batch4[N_NODES / 4];
__device__ int4  g_ecnt4[N_NODES / 4];   // in-degree (without self loop)
__device__ int   g_gptr[N_GRAPHS + 1];
__device__ float4 g_pooled4[N_GRAPHS * HID / 4];
// half feature buffers (float4-declared for 16B alignment)
__device__ float4 g_bufA[(size_t)N_NODES * HID / 8];
__device__ float4 g_bufB[(size_t)N_NODES * HID / 8];
__device__ float4 g_bufC[(size_t)N_NODES * HID / 8];

#define g_csrp   ((int*)g_csrp4)
#define g_dstv   ((int*)g_dstv4)
#define g_srcv   ((int*)g_srcv4)
#define g_rank   ((int*)g_rank4)
#define g_batch  ((int*)g_batch4)
#define g_ecnt   ((int*)g_ecnt4)
#define g_pooled ((float*)g_pooled4)

__device__ __forceinline__ __half* selbuf(int s) {
    return (__half*)(s == 0 ? g_bufA : (s == 1 ? g_bufB : g_bufC));
}

// ---------------- init: zero counters + convert x fp32->fp16 into bufB ----------------
__global__ void k_init(const float* __restrict__ x) {
    int stride = gridDim.x * blockDim.x;
    int i0 = blockIdx.x * blockDim.x + threadIdx.x;
    int4 z = make_int4(0, 0, 0, 0);
    for (int i = i0; i < N_NODES / 4; i += stride) g_ecnt4[i] = z;
    float4 z4 = make_float4(0.f, 0.f, 0.f, 0.f);
    for (int i = i0; i < N_GRAPHS * HID / 4; i += stride) g_pooled4[i] = z4;
    uint2* xh = (uint2*)g_bufB;
    const float4* xf = (const float4*)x;
    for (int i = i0; i < N_NODES * HID / 4; i += stride) {
        float4 v = xf[i];
        __half2 a = __floats2half2_rn(v.x, v.y);
        __half2 b = __floats2half2_rn(v.z, v.w);
        xh[i] = make_uint2(*(unsigned*)&a, *(unsigned*)&b);
    }
    if (i0 == 0) g_over_ctr = 0;
}

// ---------------- prep: dtype detect + convert + degree histogram + gptr ----------------
__global__ void k_prep(const int* __restrict__ ei, const int* __restrict__ bt) {
    __shared__ int s_is64;
    if (threadIdx.x == 0) {
        int zeros = 0;
#pragma unroll
        for (int i = 0; i < 64; i++)
            if (ei[2 * i + 1] == 0) zeros++;
        s_is64 = (zeros >= 48) ? 1 : 0;
    }
    __syncthreads();
    int is64 = s_is64;
    int t = blockIdx.x * blockDim.x + threadIdx.x;
    if (t < N_EDGES / 4) {
        int4 sv, dv;
        if (is64) {
            const longlong2* e = (const longlong2*)ei;
            longlong2 a = e[t * 2], b = e[t * 2 + 1];
            longlong2 c = e[N_EDGES / 2 + t * 2], d = e[N_EDGES / 2 + t * 2 + 1];
            sv = make_int4((int)a.x, (int)a.y, (int)b.x, (int)b.y);
            dv = make_int4((int)c.x, (int)c.y, (int)d.x, (int)d.y);
        } else {
            const int4* e = (const int4*)ei;
            sv = e[t];
            dv = e[N_EDGES / 4 + t];
        }
        g_srcv4[t] = sv;
        g_dstv4[t] = dv;
        int4 rk;
        rk.x = atomicAdd(&g_ecnt[dv.x], 1);
        rk.y = atomicAdd(&g_ecnt[dv.y], 1);
        rk.z = atomicAdd(&g_ecnt[dv.z], 1);
        rk.w = atomicAdd(&g_ecnt[dv.w], 1);
        g_rank4[t] = rk;
    }
    if (t < N_NODES / 4) {
        int4 bv;
        if (is64) {
            const longlong2* b = (const longlong2*)bt;
            longlong2 p = b[t * 2], q = b[t * 2 + 1];
            bv = make_int4((int)p.x, (int)p.y, (int)q.x, (int)q.y);
        } else {
            bv = ((const int4*)bt)[t];
        }
        g_batch4[t] = bv;
    }
    // graph boundaries from sorted batch (each gptr entry written exactly once)
    if (t < N_NODES) {
        int b = is64 ? (int)((const long long*)bt)[t] : bt[t];
        int pb = -1;
        if (t > 0) pb = is64 ? (int)((const long long*)bt)[t - 1] : bt[t - 1];
        for (int g = pb + 1; g <= b; g++) g_gptr[g] = t;
        if (t == N_NODES - 1)
            for (int g = b + 1; g <= N_GRAPHS; g++) g_gptr[g] = N_NODES;
    }
}

// ---------------- fill: padded scatter ----------------
__global__ void k_fill() {
    int t = blockIdx.x * blockDim.x + threadIdx.x;
    if (t >= N_EDGES / 4) return;
    int4 sv = g_srcv4[t];
    int4 dv = g_dstv4[t];
    int4 rk = g_rank4[t];
#pragma unroll
    for (int u = 0; u < 4; u++) {
        int s = (&sv.x)[u], d = (&dv.x)[u], r = (&rk.x)[u];
        if (r < PAD) {
            g_csrp[d * PAD + r] = s;
        } else {
            int p = atomicAdd(&g_over_ctr, 1);
            if (p < OVER_CAP) g_over[p] = make_int2(d, s);
        }
    }
}

// ---------------- GEMM via tensor cores: persistent, register-resident B ----------------
// Y[N,128] = X[N,128] @ W[128,128]. Each warp owns a fixed 16-col slice:
// its 8 B fragments (full K) load once per block and stay in registers.
// Blocks loop over 16-row tiles; X tile staged in smem (coalesced).
__global__ void k_gemm_wmma(int insel, int outsel, const float* __restrict__ Wf) {
    __shared__ __half sWh[128][136];
    __shared__ __half sX[16][136];
    __shared__ float  sAcc[8][16][16];
    const __half* X = selbuf(insel);
    __half* Y = selbuf(outsel);
    int tid = threadIdx.x, wid = tid >> 5, lane = tid & 31;

    // W fp32 -> fp16 smem (once per block, amortized over ~11 tiles)
    for (int i = tid; i < HID * HID; i += 256)
        sWh[i >> 7][i & 127] = __float2half(Wf[i]);
    __syncthreads();

    // preload this warp's column-slice B fragments (full K) into registers
    wmma::fragment<wmma::matrix_b, 16, 16, 16, __half, wmma::row_major> bfr[8];
#pragma unroll
    for (int kb = 0; kb < 8; kb++)
        wmma::load_matrix_sync(bfr[kb], &sWh[kb * 16][wid * 16], 136);

    int r = tid >> 4, q = tid & 15;      // X-tile stage: row, uint4-seg
    int er = lane >> 1, cb = (lane & 1) * 8;  // epilogue: row, col-chunk

    for (int tile = blockIdx.x; tile < N_TILES; tile += gridDim.x) {
        int row0 = tile * 16;
        __syncthreads();   // previous tile's sX fully consumed
        ((uint4*)&sX[r][0])[q] = ((const uint4*)X)[((size_t)(row0 + r) * 128) / 8 + q];
        __syncthreads();

        wmma::fragment<wmma::accumulator, 16, 16, 16, float> acc;
        wmma::fill_fragment(acc, 0.f);
#pragma unroll
        for (int kb = 0; kb < 8; kb++) {
            wmma::fragment<wmma::matrix_a, 16, 16, 16, __half, wmma::row_major> a;
            wmma::load_matrix_sync(a, &sX[0][kb * 16], 136);
            wmma::mma_sync(acc, a, bfr[kb], acc);
        }
        wmma::store_matrix_sync(&sAcc[wid][0][0], acc, 16, wmma::mem_row_major);
        __syncwarp();
        const float* src = &sAcc[wid][er][cb];
        __half2 h0 = __floats2half2_rn(src[0], src[1]);
        __half2 h1 = __floats2half2_rn(src[2], src[3]);
        __half2 h2 = __floats2half2_rn(src[4], src[5]);
        __half2 h3 = __floats2half2_rn(src[6], src[7]);
        uint4 v = make_uint4(*(unsigned*)&h0, *(unsigned*)&h1,
                             *(unsigned*)&h2, *(unsigned*)&h3);
        ((uint4*)Y)[(((size_t)(row0 + er)) * 128 + wid * 16 + cb) >> 3] = v;
    }
}

// ---------------- agg core: one node's GCN-aggregated row (warp-collective) ----------------
__device__ __forceinline__ float4 agg_row(const uint2* __restrict__ H2, int n, int lane,
                                          const float* __restrict__ bias) {
    int degn = g_ecnt[n];
    float din = rsqrtf((float)(degn + 1));
    uint2 hr = H2[(size_t)n * 32 + lane];
    __half2* hp = (__half2*)&hr;
    float2 f0 = __half22float2(hp[0]), f1 = __half22float2(hp[1]);
    float4 acc = make_float4(din * f0.x, din * f0.y, din * f1.x, din * f1.y);

    int m = degn < PAD ? degn : PAD;
    int idx = 0;
    float wgt = 0.f;
    if (lane < m) {
        idx = g_csrp[n * PAD + lane];
        wgt = rsqrtf((float)(g_ecnt[idx] + 1));
    }
    int j = 0;
    for (; j + 4 <= m; j += 4) {
        int s0 = __shfl_sync(0xffffffffu, idx, j);
        int s1 = __shfl_sync(0xffffffffu, idx, j + 1);
        int s2 = __shfl_sync(0xffffffffu, idx, j + 2);
        int s3 = __shfl_sync(0xffffffffu, idx, j + 3);
        float w0 = __shfl_sync(0xffffffffu, wgt, j);
        float w1 = __shfl_sync(0xffffffffu, wgt, j + 1);
        float w2 = __shfl_sync(0xffffffffu, wgt, j + 2);
        float w3 = __shfl_sync(0xffffffffu, wgt, j + 3);
        uint2 v0 = H2[(size_t)s0 * 32 + lane];
        uint2 v1 = H2[(size_t)s1 * 32 + lane];
        uint2 v2 = H2[(size_t)s2 * 32 + lane];
        uint2 v3 = H2[(size_t)s3 * 32 + lane];
        {
            __half2* p = (__half2*)&v0;
            float2 a = __half22float2(p[0]), b = __half22float2(p[1]);
            acc.x += w0 * a.x; acc.y += w0 * a.y; acc.z += w0 * b.x; acc.w += w0 * b.y;
        }
        {
            __half2* p = (__half2*)&v1;
            float2 a = __half22float2(p[0]), b = __half22float2(p[1]);
            acc.x += w1 * a.x; acc.y += w1 * a.y; acc.z += w1 * b.x; acc.w += w1 * b.y;
        }
        {
            __half2* p = (__half2*)&v2;
            float2 a = __half22float2(p[0]), b = __half22float2(p[1]);
            acc.x += w2 * a.x; acc.y += w2 * a.y; acc.z += w2 * b.x; acc.w += w2 * b.y;
        }
        {
            __half2* p = (__half2*)&v3;
            float2 a = __half22float2(p[0]), b = __half22float2(p[1]);
            acc.x += w3 * a.x; acc.y += w3 * a.y; acc.z += w3 * b.x; acc.w += w3 * b.y;
        }
    }
    for (; j < m; j++) {
        int s0 = __shfl_sync(0xffffffffu, idx, j);
        float w0 = __shfl_sync(0xffffffffu, wgt, j);
        uint2 v0 = H2[(size_t)s0 * 32 + lane];
        __half2* p = (__half2*)&v0;
        float2 a = __half22float2(p[0]), b = __half22float2(p[1]);
        acc.x += w0 * a.x; acc.y += w0 * a.y; acc.z += w0 * b.x; acc.w += w0 * b.y;
    }
    // overflow edges (rank >= PAD): only nodes with deg > PAD scan the list
    if (degn > PAD) {
        int oc = g_over_ctr;
        if (oc > OVER_CAP) oc = OVER_CAP;
        for (int i = 0; i < oc; i++) {
            int2 o = g_over[i];
            if (o.x == n) {
                float w = rsqrtf((float)(g_ecnt[o.y] + 1));
                uint2 v = H2[(size_t)o.y * 32 + lane];
                __half2* p = (__half2*)&v;
                float2 a = __half22float2(p[0]), b = __half22float2(p[1]);
                acc.x += w * a.x; acc.y += w * a.y; acc.z += w * b.x; acc.w += w * b.y;
            }
        }
    }
    float4 b4 = ((const float4*)bias)[lane];
    float4 o;
    o.x = fmaxf(din * acc.x + b4.x, 0.f);
    o.y = fmaxf(din * acc.y + b4.y, 0.f);
    o.z = fmaxf(din * acc.z + b4.z, 0.f);
    o.w = fmaxf(din * acc.w + b4.w, 0.f);
    return o;
}

// ---------------- agg layer 1 ----------------
__global__ void k_agg(int insel, int outsel, const float* __restrict__ bias) {
    const uint2* H2 = (const uint2*)selbuf(insel);
    __half* O = selbuf(outsel);
    int n = (blockIdx.x * blockDim.x + threadIdx.x) >> 5;
    int lane = threadIdx.x & 31;
    if (n >= N_NODES) return;
    float4 o = agg_row(H2, n, lane, bias);
    __half2 oa = __floats2half2_rn(o.x, o.y);
    __half2 ob = __floats2half2_rn(o.z, o.w);
    ((uint2*)O)[(size_t)n * 32 + lane] = make_uint2(*(unsigned*)&oa, *(unsigned*)&ob);
}

// ---------------- agg layer 2 fused with pool-sum ----------------
__global__ void k_agg_pool(int insel, const float* __restrict__ bias) {
    __shared__ float sRow[8][132];
    const uint2* H2 = (const uint2*)selbuf(insel);
    int tid = threadIdx.x;
    int wid = tid >> 5, lane = tid & 31;
    int n = blockIdx.x * 8 + wid;   // 6250*8 == N_NODES exactly
    float4 o = agg_row(H2, n, lane, bias);
    sRow[wid][lane * 4 + 0] = o.x;
    sRow[wid][lane * 4 + 1] = o.y;
    sRow[wid][lane * 4 + 2] = o.z;
    sRow[wid][lane * 4 + 3] = o.w;
    __syncthreads();
    if (tid < HID) {
        int c = tid;
        int nb = blockIdx.x * 8;
        int g = g_batch[nb];
        float acc = 0.f;
#pragma unroll
        for (int r = 0; r < 8; r++) {
            int gn = g_batch[nb + r];
            if (gn != g) {
                atomicAdd(&g_pooled[g * HID + c], acc);
                acc = 0.f;
                g = gn;
            }
            acc += sRow[r][c];
        }
        atomicAdd(&g_pooled[g * HID + c], acc);
    }
}

// ---------------- head: mean + lin1 + ax lin + concat + lin2 ----------------
__global__ void k_head(const float* __restrict__ ax,
                       const float* __restrict__ lin1W, const float* __restrict__ lin1b,
                       const float* __restrict__ axW, const float* __restrict__ axb,
                       const float* __restrict__ lin2W, const float* __restrict__ lin2b,
                       float* __restrict__ out) {
    int g = blockIdx.x;
    int t = threadIdx.x;  // 192
    __shared__ float sp[G_OUT];
    __shared__ float sa[AX_IN];
    __shared__ float z[G_OUT + AX_OUT];
    int cnt = g_gptr[g + 1] - g_gptr[g];
    float inv = 1.f / (float)(cnt > 1 ? cnt : 1);
    if (t < G_OUT) {
        sp[t] = g_pooled[g * HID + t] * inv;
    } else {
        sa[t - G_OUT] = ax[g * AX_IN + (t - G_OUT)];
    }
    __syncthreads();
    if (t < G_OUT) {
        float acc = lin1b[t];
#pragma unroll 8
        for (int k = 0; k < HID; k++) acc += sp[k] * lin1W[k * G_OUT + t];
        z[t] = acc;
    } else {
        int c = t - G_OUT;
        float acc = axb[c];
#pragma unroll 8
        for (int k = 0; k < AX_IN; k++) acc += sa[k] * axW[k * AX_OUT + c];
        z[t] = acc;
    }
    __syncthreads();
    if (t < OUT_CH) {
        float o = lin2b[t];
#pragma unroll 8
        for (int k = 0; k < G_OUT + AX_OUT; k++) o += z[k] * lin2W[k * OUT_CH + t];
        out[g * OUT_CH + t] = o;
    }
}

// ---------------- launch ----------------
extern "C" void kernel_launch(void* const* d_in, const int* in_sizes, int n_in,
                              void* d_out, int out_size) {
    const float* x     = (const float*)d_in[0];
    const int*   ei    = (const int*)d_in[1];
    const int*   bt    = (const int*)d_in[2];
    const float* ax    = (const float*)d_in[3];
    const float* W1    = (const float*)d_in[4];
    const float* b1    = (const float*)d_in[5];
    const float* W2    = (const float*)d_in[6];
    const float* b2    = (const float*)d_in[7];
    const float* lin1W = (const float*)d_in[8];
    const float* lin1b = (const float*)d_in[9];
    const float* axW   = (const float*)d_in[10];
    const float* axb   = (const float*)d_in[11];
    const float* lin2W = (const float*)d_in[12];
    const float* lin2b = (const float*)d_in[13];
    float* out = (float*)d_out;

    const int EB4 = (N_EDGES / 4 + 255) / 256;   // 625

    k_init<<<2048, 256>>>(x);                     // zero + x -> fp16 (bufB)
    k_prep<<<EB4, 256>>>(ei, bt);                 // convert + hist/rank + gptr
    k_fill<<<EB4, 256>>>();                       // padded CSR scatter
    k_gemm_wmma<<<GEMM_BLOCKS, 256>>>(1, 0, W1);  // xh(B) @ W1 -> A
    k_agg<<<(N_NODES * 32) / 256, 256>>>(0, 1, b1);   // agg(A) -> B (relu)
    k_gemm_wmma<<<GEMM_BLOCKS, 256>>>(1, 2, W2);  // B @ W2 -> C
    k_agg_pool<<<N_NODES / 8, 256>>>(2, b2);      // agg(C) + pool-sum
    k_head<<<N_GRAPHS, 192>>>(ax, lin1W, lin1b, axW, axb, lin2W, lin2b, out);
}